// round 14
// baseline (speedup 1.0000x reference)
#include <cuda_runtime.h>
#include <cuda_fp16.h>
#include <cstdint>

#define NPTS 16384
#define BATCH 16
#define INC 7
typedef unsigned long long u64;
typedef unsigned int u32;

// ---------------- scratch ----------------
__device__ u32                g_hhi[(size_t)BATCH * 64 * NPTS]; // (b, kp, i)
__device__ u32                g_hlo[(size_t)BATCH * 64 * NPTS];
__device__ u32                g_wphi[1024 * 64];                // W4 (c, kp), x64
__device__ u32                g_wplo[1024 * 64];
__device__ u32                g_w1hi[64 * 32],  g_w1lo[64 * 32];   // W1 x64
__device__ u32                g_w2hi[64 * 32],  g_w2lo[64 * 32];   // W2 x64
__device__ u32                g_w3hi[128 * 32], g_w3lo[128 * 32];  // W3 x64
__device__ unsigned char      g_gid[BATCH * NPTS];
__device__ unsigned long long g_pmax[BATCH * 1024];
__device__ unsigned int       g_gmax[4 * 1024];
__device__ float              g_u1[17 * 512];

__device__ __forceinline__ void split_limbs(float v, unsigned short& hi, unsigned short& lo) {
    __half h = __float2half_rn(v);
    float r = v - __half2float(h);
    __half l = __float2half_rn(r);
    hi = __half_as_ushort(h);
    lo = __half_as_ushort(l);
}
__device__ __forceinline__ void split_pair(float a, float b, u32& hi, u32& lo) {
    unsigned short h0, l0, h1, l1;
    split_limbs(a, h0, l0); split_limbs(b, h1, l1);
    hi = (u32)h0 | ((u32)h1 << 16);
    lo = (u32)l0 | ((u32)l1 << 16);
}
__device__ __forceinline__ void mma16(float* d, const u32* a, const u32* b) {
    asm volatile("mma.sync.aligned.m16n8k16.row.col.f32.f16.f16.f32 "
                 "{%0,%1,%2,%3}, {%4,%5,%6,%7}, {%8,%9}, {%0,%1,%2,%3};"
                 : "+f"(d[0]), "+f"(d[1]), "+f"(d[2]), "+f"(d[3])
                 : "r"(a[0]), "r"(a[1]), "r"(a[2]), "r"(a[3]), "r"(b[0]), "r"(b[1]));
}
__device__ __forceinline__ u32 smem_u32(const void* p) {
    u32 a; asm("{ .reg .u64 t; cvta.to.shared.u64 t, %1; cvt.u32.u64 %0, t; }" : "=r"(a) : "l"(p)); return a;
}
#define CP_ASYNC16(dst, src) asm volatile("cp.async.cg.shared.global [%0], [%1], 16;" :: "r"(dst), "l"(src) : "memory")
#define CP_COMMIT()  asm volatile("cp.async.commit_group;" ::: "memory")
#define CP_WAIT0()   asm volatile("cp.async.wait_group 0;" ::: "memory")
#define CP_WAIT1()   asm volatile("cp.async.wait_group 1;" ::: "memory")

// ================= kernel Wall: weight limb-split + reduction-buffer init =================
__global__ void kWall(const float* __restrict__ wl1, const float* __restrict__ wl2,
                      const float* __restrict__ wl3, const float* __restrict__ wl4) {
    int T = blockIdx.x * blockDim.x + threadIdx.x;
    if (T < BATCH * 1024) g_pmax[T] = 0ull;
    if (T < 4 * 1024) g_gmax[T] = 0u;
    const float* src; u32 *dhi, *dlo; int c, kp, K;
    if (T < 2048)       { src = wl1; dhi = g_w1hi; dlo = g_w1lo; int t = T;          c = t >> 5; kp = t & 31; K = 64;  dhi += t; dlo += t; }
    else if (T < 4096)  { src = wl2; dhi = g_w2hi; dlo = g_w2lo; int t = T - 2048;   c = t >> 5; kp = t & 31; K = 64;  dhi += t; dlo += t; }
    else if (T < 8192)  { src = wl3; dhi = g_w3hi; dlo = g_w3lo; int t = T - 4096;   c = t >> 5; kp = t & 31; K = 64;  dhi += t; dlo += t; }
    else if (T < 73728) { src = wl4; dhi = g_wphi; dlo = g_wplo; int t = T - 8192;   c = t >> 6; kp = t & 63; K = 128; dhi += t; dlo += t; }
    else return;
    u32 hi, lo;
    split_pair(src[c * K + 2 * kp] * 64.0f, src[c * K + 2 * kp + 1] * 64.0f, hi, lo);
    *dhi = hi; *dlo = lo;
}

// ================= kernel A: L0 scalar + L1/L2/L3 as 3-pass split-fp16 MMA (R13 proven) =================
#define OFF_WBA 0
#define OFF_WBB 9216
#define OFF_ACTA 13824
#define OFF_ACTB 22528
#define OFF_STAGE 31232
#define KA_SMEM_U32 47872
#define ACT_PL 4352
#define AST 136
#define WST 36

__device__ __forceinline__ void cpw(u32 dst, const u32* hi, const u32* lo, int C, int tid) {
    const int chunks = C * 8;
    for (int j = tid; j < 2 * chunks; j += 256) {
        int plane = (j >= chunks);
        int r = (j - plane * chunks) >> 3;
        int q = (j & 7) * 4;
        const u32* src = (plane ? lo : hi) + r * 32 + q;
        CP_ASYNC16(dst + (u32)(plane * C * WST + r * WST + q) * 4, src);
    }
}

template <int MT>
__device__ __forceinline__ void layer_mma(const u32* __restrict__ wb, int wplane,
                                          const u32* __restrict__ act,
                                          float* __restrict__ stage,
                                          const float* __restrict__ bias, int tid) {
    const int lane = tid & 31, wrp = tid >> 5;
    const int mw = wrp >> 1, nw = wrp & 1;
    const int gid4 = lane >> 2, tig = lane & 3;
    const int cw = mw * (MT * 16), pw = nw * 64;

    float acc[MT][8][4];
#pragma unroll
    for (int mt = 0; mt < MT; mt++)
#pragma unroll
        for (int nt = 0; nt < 8; nt++)
#pragma unroll
            for (int j = 0; j < 4; j++) acc[mt][nt][j] = 0.0f;

#pragma unroll
    for (int kk = 0; kk < 4; kk++) {
        const int kpb = kk * 8;
        u32 ahi[MT][4], alo[MT][4];
#pragma unroll
        for (int mt = 0; mt < MT; mt++) {
            const int r0 = cw + mt * 16 + gid4;
#pragma unroll
            for (int q = 0; q < 4; q++) {
                const int rr = r0 + (q & 1) * 8;
                const int kq = kpb + tig + (q >> 1) * 4;
                ahi[mt][q] = wb[rr * WST + kq];
                alo[mt][q] = wb[wplane + rr * WST + kq];
            }
        }
        u32 bhi[8][2], blo[8][2];
#pragma unroll
        for (int nt = 0; nt < 8; nt++) {
            const int pp = pw + nt * 8 + gid4;
#pragma unroll
            for (int q = 0; q < 2; q++) {
                const int kr = kpb + tig + q * 4;
                bhi[nt][q] = act[kr * AST + pp];
                blo[nt][q] = act[ACT_PL + kr * AST + pp];
            }
        }
#pragma unroll
        for (int mt = 0; mt < MT; mt++)
#pragma unroll
            for (int nt = 0; nt < 8; nt++) {
                mma16(acc[mt][nt], ahi[mt], bhi[nt]);
                mma16(acc[mt][nt], ahi[mt], blo[nt]);
                mma16(acc[mt][nt], alo[mt], bhi[nt]);
            }
    }
#pragma unroll
    for (int mt = 0; mt < MT; mt++)
#pragma unroll
        for (int hf = 0; hf < 2; hf++) {
            const int c = cw + mt * 16 + gid4 + hf * 8;
            const float bias_c = __ldg(&bias[c]);
#pragma unroll
            for (int nt = 0; nt < 8; nt++)
#pragma unroll
                for (int jj = 0; jj < 2; jj++) {
                    float val = fmaxf(fmaf(acc[mt][nt][hf * 2 + jj], 0.015625f, bias_c), 0.0f);
                    stage[c * 130 + pw + nt * 8 + tig * 2 + jj] = val;
                }
        }
}

__global__ __launch_bounds__(256, 1)
void kA(const float* __restrict__ points,
        const float* __restrict__ wl0, const float* __restrict__ bl0,
        const float* __restrict__ bl1, const float* __restrict__ bl2,
        const float* __restrict__ bl3) {
    extern __shared__ u32 smu[];
    u32* wbufA = smu + OFF_WBA;
    u32* wbufB = smu + OFF_WBB;
    u32* actA  = smu + OFF_ACTA;
    u32* actB  = smu + OFF_ACTB;
    float* stage = reinterpret_cast<float*>(smu + OFF_STAGE);
    const u32 sbase = smem_u32(smu);
    const int tid = threadIdx.x;
    const int bid = blockIdx.x;
    const int b = bid >> 7;
    const int pbase = (bid & 127) * 128;

    cpw(sbase + OFF_WBA * 4, g_w1hi, g_w1lo, 64, tid);
    CP_COMMIT();

    for (int i = tid; i < 448; i += 256) stage[i] = wl0[i];
    for (int i = tid; i < 64; i += 256) stage[448 + i] = bl0[i];
    __syncthreads();

    {
        const int pt = tid & 127, seg = tid >> 7;
        const float* ptp = points + (size_t)b * INC * NPTS + pbase + pt;
        float x[INC];
#pragma unroll
        for (int c = 0; c < INC; c++) x[c] = ptp[(size_t)c * NPTS];
        if (seg == 0) {
            int g = 0; float bv = x[3];
            if (x[4] > bv) { bv = x[4]; g = 1; }
            if (x[5] > bv) { bv = x[5]; g = 2; }
            if (x[6] > bv) { bv = x[6]; g = 3; }
            g_gid[b * NPTS + pbase + pt] = (unsigned char)g;
        }
#pragma unroll 4
        for (int kp = seg * 16; kp < seg * 16 + 16; kp++) {
            const int c = 2 * kp;
            const float* w0 = stage + c * 7;
            const float* w1 = w0 + 7;
            float s0 = stage[448 + c], s1 = stage[448 + c + 1];
#pragma unroll
            for (int k = 0; k < INC; k++) { s0 = fmaf(w0[k], x[k], s0); s1 = fmaf(w1[k], x[k], s1); }
            u32 hi, lo;
            split_pair(fmaxf(s0, 0.0f), fmaxf(s1, 0.0f), hi, lo);
            actA[kp * AST + pt] = hi;
            actA[ACT_PL + kp * AST + pt] = lo;
        }
    }
    CP_WAIT0();
    __syncthreads();

    cpw(sbase + OFF_WBB * 4, g_w2hi, g_w2lo, 64, tid);
    CP_COMMIT();

    layer_mma<1>(wbufA, 64 * WST, actA, stage, bl1, tid);
    __syncthreads();
    {
        const int pt = tid & 127, seg = tid >> 7;
#pragma unroll 4
        for (int kp = seg * 16; kp < seg * 16 + 16; kp++) {
            u32 hi, lo;
            split_pair(stage[(2 * kp) * 130 + pt], stage[(2 * kp + 1) * 130 + pt], hi, lo);
            actB[kp * AST + pt] = hi;
            actB[ACT_PL + kp * AST + pt] = lo;
        }
    }
    cpw(sbase + OFF_WBA * 4, g_w3hi, g_w3lo, 128, tid);
    CP_COMMIT();
    CP_WAIT1();
    __syncthreads();

    layer_mma<1>(wbufB, 64 * WST, actB, stage, bl2, tid);
    __syncthreads();
    {
        const int pt = tid & 127, seg = tid >> 7;
#pragma unroll 4
        for (int kp = seg * 16; kp < seg * 16 + 16; kp++) {
            u32 hi, lo;
            split_pair(stage[(2 * kp) * 130 + pt], stage[(2 * kp + 1) * 130 + pt], hi, lo);
            actA[kp * AST + pt] = hi;
            actA[ACT_PL + kp * AST + pt] = lo;
        }
    }
    CP_WAIT0();
    __syncthreads();

    layer_mma<2>(wbufA, 128 * WST, actA, stage, bl3, tid);
    __syncthreads();
    {
        const int pt = tid & 127, seg = tid >> 7;
#pragma unroll 4
        for (int kp = seg * 32; kp < seg * 32 + 32; kp++) {
            u32 hi, lo;
            split_pair(stage[(2 * kp) * 130 + pt], stage[(2 * kp + 1) * 130 + pt], hi, lo);
            g_hhi[((size_t)b * 64 + kp) * NPTS + pbase + pt] = hi;
            g_hlo[((size_t)b * 64 + kp) * NPTS + pbase + pt] = lo;
        }
    }
}

// ================= kernel B: R12 mainloop + slimmed epilogue (float+idx, hoisted group tests) =================
#define WS2 68
#define HS2 136
#define KB_W_U (2 * 128 * WS2)
#define KB_H_U (2 * 64 * HS2)
#define KB_SMEM_BYTES ((KB_W_U + 2 * KB_H_U) * 4)

__global__ __launch_bounds__(256, 1)
void kB(const float* __restrict__ bl4) {
    extern __shared__ float smf[];
    u32* swp = reinterpret_cast<u32*>(smf);
    u32* hbuf0 = swp + KB_W_U;
    u32* hbuf1 = hbuf0 + KB_H_U;
    __shared__ unsigned char gid_s[128];

    const int tid = threadIdx.x;
    const int bid = blockIdx.x;
    const int b  = bid >> 6;
    const int pg = (bid >> 3) & 7;
    const int cc = bid & 7;
    const int c0 = cc * 128;

#pragma unroll
    for (int j = 0; j < 8; j++) {
        int idx = j * 256 + tid;
        int r = idx >> 4, q = (idx & 15) * 4;
        uint4 vh = *reinterpret_cast<const uint4*>(g_wphi + (size_t)(c0 + r) * 64 + q);
        uint4 vl = *reinterpret_cast<const uint4*>(g_wplo + (size_t)(c0 + r) * 64 + q);
        *reinterpret_cast<uint4*>(&swp[r * WS2 + q]) = vh;
        *reinterpret_cast<uint4*>(&swp[128 * WS2 + r * WS2 + q]) = vl;
    }

    const u32 hadd[2] = { smem_u32(hbuf0), smem_u32(hbuf1) };
    {
        const int pbase = pg * 2048;
#pragma unroll
        for (int j = 0; j < 16; j++) {
            int idx = j * 256 + tid;
            int row = idx >> 5, q = (idx & 31) * 4;
            const u32* src = (row < 64)
                ? g_hhi + ((size_t)b * 64 + row) * NPTS + pbase + q
                : g_hlo + ((size_t)b * 64 + (row - 64)) * NPTS + pbase + q;
            CP_ASYNC16(hadd[0] + (u32)(row * HS2 + q) * 4, src);
        }
        CP_COMMIT();
    }

    const int lane = tid & 31, wrp = tid >> 5;
    const int mw = wrp >> 1;
    const int nw = wrp & 1;
    const int gid4 = lane >> 2, tig = lane & 3;
    const int cw = mw * 32, pw = nw * 64;

    float biasr[2][2];
    float bv[2][2];
    u32 bidx[2][2];
    float gm[2][2][4];
#pragma unroll
    for (int mt = 0; mt < 2; mt++)
#pragma unroll
        for (int hf = 0; hf < 2; hf++) {
            biasr[mt][hf] = __ldg(&bl4[c0 + cw + mt * 16 + gid4 + hf * 8]);
            bv[mt][hf] = -1.0f;
            bidx[mt][hf] = 0u;
#pragma unroll
            for (int g = 0; g < 4; g++) gm[mt][hf][g] = 0.0f;
        }

#pragma unroll 1
    for (int t = 0; t < 16; t++) {
        const int pbase = (pg * 16 + t) * 128;
        u32* shp = (t & 1) ? hbuf1 : hbuf0;
        if (t + 1 < 16) {
            const int pn = (pg * 16 + t + 1) * 128;
            const u32 dsta = hadd[(t + 1) & 1];
#pragma unroll
            for (int j = 0; j < 16; j++) {
                int idx = j * 256 + tid;
                int row = idx >> 5, q = (idx & 31) * 4;
                const u32* src = (row < 64)
                    ? g_hhi + ((size_t)b * 64 + row) * NPTS + pn + q
                    : g_hlo + ((size_t)b * 64 + (row - 64)) * NPTS + pn + q;
                CP_ASYNC16(dsta + (u32)(row * HS2 + q) * 4, src);
            }
            CP_COMMIT();
            CP_WAIT1();
        } else {
            CP_WAIT0();
        }
        if (tid < 128) gid_s[tid] = g_gid[b * NPTS + pbase + tid];
        __syncthreads();

        float acc[2][8][4];
#pragma unroll
        for (int mt = 0; mt < 2; mt++)
#pragma unroll
            for (int nt = 0; nt < 8; nt++)
#pragma unroll
                for (int j = 0; j < 4; j++) acc[mt][nt][j] = 0.0f;

        const u32* swhi = swp;
        const u32* swlo = swp + 128 * WS2;
        const u32* shhi = shp;
        const u32* shlo = shp + 64 * HS2;

#pragma unroll 1
        for (int kk = 0; kk < 8; kk++) {
            const int kpb = kk * 8;
            u32 ahi[2][4], alo[2][4];
#pragma unroll
            for (int mt = 0; mt < 2; mt++) {
                const int r0 = cw + mt * 16 + gid4;
#pragma unroll
                for (int q = 0; q < 4; q++) {
                    const int rr = r0 + (q & 1) * 8;
                    const int kq = kpb + tig + (q >> 1) * 4;
                    ahi[mt][q] = swhi[rr * WS2 + kq];
                    alo[mt][q] = swlo[rr * WS2 + kq];
                }
            }
            u32 bhi[8][2], blo[8][2];
#pragma unroll
            for (int nt = 0; nt < 8; nt++) {
                const int pp = pw + nt * 8 + gid4;
#pragma unroll
                for (int q = 0; q < 2; q++) {
                    const int kr = kpb + tig + q * 4;
                    bhi[nt][q] = shhi[kr * HS2 + pp];
                    blo[nt][q] = shlo[kr * HS2 + pp];
                }
            }
#pragma unroll
            for (int mt = 0; mt < 2; mt++)
#pragma unroll
                for (int nt = 0; nt < 8; nt++) {
                    mma16(acc[mt][nt], ahi[mt], bhi[nt]);
                    mma16(acc[mt][nt], ahi[mt], blo[nt]);
                    mma16(acc[mt][nt], alo[mt], bhi[nt]);
                }
        }

        // epilogue: point-outer, channel-inner; per-thread point index strictly increasing
#pragma unroll
        for (int nt = 0; nt < 8; nt++)
#pragma unroll
            for (int jj = 0; jj < 2; jj++) {
                const int pl = pw + nt * 8 + tig * 2 + jj;
                const int gi = gid_s[pl];
                const u32 gidx = (u32)(pbase + pl);
#pragma unroll
                for (int mt = 0; mt < 2; mt++)
#pragma unroll
                    for (int hf = 0; hf < 2; hf++) {
                        float val = fmaxf(fmaf(acc[mt][nt][hf * 2 + jj], 0.015625f, biasr[mt][hf]), 0.0f);
                        if (val > bv[mt][hf]) { bv[mt][hf] = val; bidx[mt][hf] = gidx; }
                        if (gi == 0) gm[mt][hf][0] = fmaxf(gm[mt][hf][0], val);
                        if (gi == 1) gm[mt][hf][1] = fmaxf(gm[mt][hf][1], val);
                        if (gi == 2) gm[mt][hf][2] = fmaxf(gm[mt][hf][2], val);
                        if (gi == 3) gm[mt][hf][3] = fmaxf(gm[mt][hf][3], val);
                    }
            }
        __syncthreads();
    }

    // single staging + reduce + atomics
    u64* skey = reinterpret_cast<u64*>(hbuf0);
    float* sg = reinterpret_cast<float*>(skey + 1024);
    const int slot = nw * 4 + tig;
#pragma unroll
    for (int mt = 0; mt < 2; mt++)
#pragma unroll
        for (int hf = 0; hf < 2; hf++) {
            const int c = cw + mt * 16 + gid4 + hf * 8;
            skey[c * 8 + slot] = ((u64)__float_as_uint(bv[mt][hf]) << 32) |
                                 (u64)(0xFFFFFFFFu - bidx[mt][hf]);
#pragma unroll
            for (int g = 0; g < 4; g++) sg[(c * 8 + slot) * 4 + g] = gm[mt][hf][g];
        }
    __syncthreads();

    if (tid < 128) {
        const int c = tid;
        u64 m = skey[c * 8];
        float mg[4] = { sg[c * 32 + 0], sg[c * 32 + 1], sg[c * 32 + 2], sg[c * 32 + 3] };
#pragma unroll
        for (int q = 1; q < 8; q++) {
            u64 e = skey[c * 8 + q];
            if (e > m) m = e;
#pragma unroll
            for (int g = 0; g < 4; g++) mg[g] = fmaxf(mg[g], sg[(c * 8 + q) * 4 + g]);
        }
        atomicMax(&g_pmax[b * 1024 + c0 + c], m);
#pragma unroll
        for (int g = 0; g < 4; g++)
            atomicMax(&g_gmax[g * 1024 + c0 + c], __float_as_uint(mg[g]));
    }
}

// ---------------- tail MLPs (unchanged) ----------------
__global__ void kC1(const float* __restrict__ wg0, const float* __restrict__ bg0,
                    const float* __restrict__ wgr0, const float* __restrict__ bgr0,
                    float* __restrict__ out) {
    const int gtid = blockIdx.x * blockDim.x + threadIdx.x;
    if (gtid < BATCH * 1024) {
        unsigned long long pv = g_pmax[gtid];
        out[4096 + gtid] = (float)(0xFFFFFFFFu - (unsigned int)(pv & 0xFFFFFFFFull));
    }
    const int wid = gtid >> 5;
    const int lane = gtid & 31;
    const int row = wid >> 9;
    const int j = wid & 511;
    if (row > 16) return;
    float s = 0.0f;
    if (row < 16) {
        const float* wr = wg0 + (size_t)j * 1024;
        const unsigned long long* pbuf = g_pmax + row * 1024;
        for (int k = lane; k < 1024; k += 32)
            s = fmaf(wr[k], __uint_as_float((unsigned int)(pbuf[k] >> 32)), s);
    } else {
        const float* wr = wgr0 + (size_t)j * 4096;
        for (int k = lane; k < 4096; k += 32)
            s = fmaf(wr[k], __uint_as_float(g_gmax[k]), s);
    }
#pragma unroll
    for (int o = 16; o; o >>= 1) s += __shfl_xor_sync(0xFFFFFFFFu, s, o);
    if (lane == 0) {
        float bb = (row < 16) ? bg0[j] : bgr0[j];
        g_u1[row * 512 + j] = fmaxf(s + bb, 0.0f);
    }
}

__global__ void kC2(const float* __restrict__ wg1, const float* __restrict__ bg1,
                    const float* __restrict__ wgr1, const float* __restrict__ bgr1,
                    float* __restrict__ out) {
    const int gtid = blockIdx.x * blockDim.x + threadIdx.x;
    const int wid = gtid >> 5;
    const int lane = gtid & 31;
    const int row = wid >> 7;
    const int j = wid & 127;
    if (row > 16) return;
    const float* wr = ((row < 16) ? wg1 : wgr1) + (size_t)j * 512;
    const float* in = g_u1 + row * 512;
    float s = 0.0f;
    for (int k = lane; k < 512; k += 32) s = fmaf(wr[k], in[k], s);
#pragma unroll
    for (int o = 16; o; o >>= 1) s += __shfl_xor_sync(0xFFFFFFFFu, s, o);
    s = __shfl_sync(0xFFFFFFFFu, s, 0);
    float bb = (row < 16) ? bg1[j] : bgr1[j];
    float val = fmaxf(s + bb, 0.0f);
    if (row < 16) {
        if (lane == 0) out[row * 256 + 128 + j] = val;
    } else {
        if (lane < 16) out[lane * 256 + j] = val;
    }
}

// ---------------- launch ----------------
extern "C" void kernel_launch(void* const* d_in, const int* in_sizes, int n_in,
                              void* d_out, int out_size) {
    const float* points = (const float*)d_in[0];
    const float* wl0 = (const float*)d_in[1];  const float* bl0 = (const float*)d_in[2];
    const float* wl1 = (const float*)d_in[3];  const float* bl1 = (const float*)d_in[4];
    const float* wl2 = (const float*)d_in[5];  const float* bl2 = (const float*)d_in[6];
    const float* wl3 = (const float*)d_in[7];  const float* bl3 = (const float*)d_in[8];
    const float* wl4 = (const float*)d_in[9];  const float* bl4 = (const float*)d_in[10];
    const float* wg0 = (const float*)d_in[11]; const float* bg0 = (const float*)d_in[12];
    const float* wg1 = (const float*)d_in[13]; const float* bg1 = (const float*)d_in[14];
    const float* wgr0 = (const float*)d_in[15]; const float* bgr0 = (const float*)d_in[16];
    const float* wgr1 = (const float*)d_in[17]; const float* bgr1 = (const float*)d_in[18];
    float* out = (float*)d_out;

    cudaFuncSetAttribute(kA, cudaFuncAttributeMaxDynamicSharedMemorySize,
                         KA_SMEM_U32 * (int)sizeof(u32));
    cudaFuncSetAttribute(kB, cudaFuncAttributeMaxDynamicSharedMemorySize, KB_SMEM_BYTES);

    kWall<<<288, 256>>>(wl1, wl2, wl3, wl4);
    kA<<<BATCH * NPTS / 128, 256, KA_SMEM_U32 * sizeof(u32)>>>(
        points, wl0, bl0, bl1, bl2, bl3);
    kB<<<1024, 256, KB_SMEM_BYTES>>>(bl4);
    kC1<<<1088, 256>>>(wg0, bg0, wgr0, bgr0, out);
    kC2<<<272, 256>>>(wg1, bg1, wgr1, bgr1, out);
}

// round 15
// speedup vs baseline: 1.5592x; 1.5592x over previous
#include <cuda_runtime.h>
#include <cuda_fp16.h>
#include <cstdint>

#define NPTS 16384
#define BATCH 16
#define INC 7
typedef unsigned long long u64;
typedef unsigned int u32;

// ---------------- scratch ----------------
__device__ u32                g_hhi[(size_t)BATCH * 64 * NPTS]; // (b, kp, i)
__device__ u32                g_hlo[(size_t)BATCH * 64 * NPTS];
__device__ u32                g_wphi[1024 * 64];                // W4 (c, kp), x64
__device__ u32                g_wplo[1024 * 64];
__device__ u32                g_w1hi[64 * 32],  g_w1lo[64 * 32];   // W1 x64
__device__ u32                g_w2hi[64 * 32],  g_w2lo[64 * 32];   // W2 x64
__device__ u32                g_w3hi[128 * 32], g_w3lo[128 * 32];  // W3 x64
__device__ unsigned char      g_gid[BATCH * NPTS];
__device__ unsigned long long g_pmax[BATCH * 1024];
__device__ unsigned int       g_gmax[4 * 1024];
__device__ float              g_u1[17 * 512];

__device__ __forceinline__ void split_limbs(float v, unsigned short& hi, unsigned short& lo) {
    __half h = __float2half_rn(v);
    float r = v - __half2float(h);
    __half l = __float2half_rn(r);
    hi = __half_as_ushort(h);
    lo = __half_as_ushort(l);
}
__device__ __forceinline__ void split_pair(float a, float b, u32& hi, u32& lo) {
    unsigned short h0, l0, h1, l1;
    split_limbs(a, h0, l0); split_limbs(b, h1, l1);
    hi = (u32)h0 | ((u32)h1 << 16);
    lo = (u32)l0 | ((u32)l1 << 16);
}
__device__ __forceinline__ void mma16(float* d, const u32* a, const u32* b) {
    asm volatile("mma.sync.aligned.m16n8k16.row.col.f32.f16.f16.f32 "
                 "{%0,%1,%2,%3}, {%4,%5,%6,%7}, {%8,%9}, {%0,%1,%2,%3};"
                 : "+f"(d[0]), "+f"(d[1]), "+f"(d[2]), "+f"(d[3])
                 : "r"(a[0]), "r"(a[1]), "r"(a[2]), "r"(a[3]), "r"(b[0]), "r"(b[1]));
}
__device__ __forceinline__ u32 smem_u32(const void* p) {
    u32 a; asm("{ .reg .u64 t; cvta.to.shared.u64 t, %1; cvt.u32.u64 %0, t; }" : "=r"(a) : "l"(p)); return a;
}
#define CP_ASYNC16(dst, src) asm volatile("cp.async.cg.shared.global [%0], [%1], 16;" :: "r"(dst), "l"(src) : "memory")
#define CP_COMMIT()  asm volatile("cp.async.commit_group;" ::: "memory")
#define CP_WAIT0()   asm volatile("cp.async.wait_group 0;" ::: "memory")
#define CP_WAIT1()   asm volatile("cp.async.wait_group 1;" ::: "memory")

// ================= kernel Wall: weight limb-split + reduction-buffer init =================
__global__ void kWall(const float* __restrict__ wl1, const float* __restrict__ wl2,
                      const float* __restrict__ wl3, const float* __restrict__ wl4) {
    int T = blockIdx.x * blockDim.x + threadIdx.x;
    if (T < BATCH * 1024) g_pmax[T] = 0ull;
    if (T < 4 * 1024) g_gmax[T] = 0u;
    const float* src; u32 *dhi, *dlo; int c, kp, K;
    if (T < 2048)       { src = wl1; dhi = g_w1hi; dlo = g_w1lo; int t = T;          c = t >> 5; kp = t & 31; K = 64;  dhi += t; dlo += t; }
    else if (T < 4096)  { src = wl2; dhi = g_w2hi; dlo = g_w2lo; int t = T - 2048;   c = t >> 5; kp = t & 31; K = 64;  dhi += t; dlo += t; }
    else if (T < 8192)  { src = wl3; dhi = g_w3hi; dlo = g_w3lo; int t = T - 4096;   c = t >> 5; kp = t & 31; K = 64;  dhi += t; dlo += t; }
    else if (T < 73728) { src = wl4; dhi = g_wphi; dlo = g_wplo; int t = T - 8192;   c = t >> 6; kp = t & 63; K = 128; dhi += t; dlo += t; }
    else return;
    u32 hi, lo;
    split_pair(src[c * K + 2 * kp] * 64.0f, src[c * K + 2 * kp + 1] * 64.0f, hi, lo);
    *dhi = hi; *dlo = lo;
}

// ================= kernel A: L0 scalar + L1/L2/L3 as 3-pass split-fp16 MMA (R13 proven) =================
#define OFF_WBA 0
#define OFF_WBB 9216
#define OFF_ACTA 13824
#define OFF_ACTB 22528
#define OFF_STAGE 31232
#define KA_SMEM_U32 47872
#define ACT_PL 4352
#define AST 136
#define WST 36

__device__ __forceinline__ void cpw(u32 dst, const u32* hi, const u32* lo, int C, int tid) {
    const int chunks = C * 8;
    for (int j = tid; j < 2 * chunks; j += 256) {
        int plane = (j >= chunks);
        int r = (j - plane * chunks) >> 3;
        int q = (j & 7) * 4;
        const u32* src = (plane ? lo : hi) + r * 32 + q;
        CP_ASYNC16(dst + (u32)(plane * C * WST + r * WST + q) * 4, src);
    }
}

template <int MT>
__device__ __forceinline__ void layer_mma(const u32* __restrict__ wb, int wplane,
                                          const u32* __restrict__ act,
                                          float* __restrict__ stage,
                                          const float* __restrict__ bias, int tid) {
    const int lane = tid & 31, wrp = tid >> 5;
    const int mw = wrp >> 1, nw = wrp & 1;
    const int gid4 = lane >> 2, tig = lane & 3;
    const int cw = mw * (MT * 16), pw = nw * 64;

    float acc[MT][8][4];
#pragma unroll
    for (int mt = 0; mt < MT; mt++)
#pragma unroll
        for (int nt = 0; nt < 8; nt++)
#pragma unroll
            for (int j = 0; j < 4; j++) acc[mt][nt][j] = 0.0f;

#pragma unroll
    for (int kk = 0; kk < 4; kk++) {
        const int kpb = kk * 8;
        u32 ahi[MT][4], alo[MT][4];
#pragma unroll
        for (int mt = 0; mt < MT; mt++) {
            const int r0 = cw + mt * 16 + gid4;
#pragma unroll
            for (int q = 0; q < 4; q++) {
                const int rr = r0 + (q & 1) * 8;
                const int kq = kpb + tig + (q >> 1) * 4;
                ahi[mt][q] = wb[rr * WST + kq];
                alo[mt][q] = wb[wplane + rr * WST + kq];
            }
        }
        u32 bhi[8][2], blo[8][2];
#pragma unroll
        for (int nt = 0; nt < 8; nt++) {
            const int pp = pw + nt * 8 + gid4;
#pragma unroll
            for (int q = 0; q < 2; q++) {
                const int kr = kpb + tig + q * 4;
                bhi[nt][q] = act[kr * AST + pp];
                blo[nt][q] = act[ACT_PL + kr * AST + pp];
            }
        }
#pragma unroll
        for (int mt = 0; mt < MT; mt++)
#pragma unroll
            for (int nt = 0; nt < 8; nt++) {
                mma16(acc[mt][nt], ahi[mt], bhi[nt]);
                mma16(acc[mt][nt], ahi[mt], blo[nt]);
                mma16(acc[mt][nt], alo[mt], bhi[nt]);
            }
    }
#pragma unroll
    for (int mt = 0; mt < MT; mt++)
#pragma unroll
        for (int hf = 0; hf < 2; hf++) {
            const int c = cw + mt * 16 + gid4 + hf * 8;
            const float bias_c = __ldg(&bias[c]);
#pragma unroll
            for (int nt = 0; nt < 8; nt++)
#pragma unroll
                for (int jj = 0; jj < 2; jj++) {
                    float val = fmaxf(fmaf(acc[mt][nt][hf * 2 + jj], 0.015625f, bias_c), 0.0f);
                    stage[c * 130 + pw + nt * 8 + tig * 2 + jj] = val;
                }
        }
}

__global__ __launch_bounds__(256, 1)
void kA(const float* __restrict__ points,
        const float* __restrict__ wl0, const float* __restrict__ bl0,
        const float* __restrict__ bl1, const float* __restrict__ bl2,
        const float* __restrict__ bl3) {
    extern __shared__ u32 smu[];
    u32* wbufA = smu + OFF_WBA;
    u32* wbufB = smu + OFF_WBB;
    u32* actA  = smu + OFF_ACTA;
    u32* actB  = smu + OFF_ACTB;
    float* stage = reinterpret_cast<float*>(smu + OFF_STAGE);
    const u32 sbase = smem_u32(smu);
    const int tid = threadIdx.x;
    const int bid = blockIdx.x;
    const int b = bid >> 7;
    const int pbase = (bid & 127) * 128;

    cpw(sbase + OFF_WBA * 4, g_w1hi, g_w1lo, 64, tid);
    CP_COMMIT();

    for (int i = tid; i < 448; i += 256) stage[i] = wl0[i];
    for (int i = tid; i < 64; i += 256) stage[448 + i] = bl0[i];
    __syncthreads();

    {
        const int pt = tid & 127, seg = tid >> 7;
        const float* ptp = points + (size_t)b * INC * NPTS + pbase + pt;
        float x[INC];
#pragma unroll
        for (int c = 0; c < INC; c++) x[c] = ptp[(size_t)c * NPTS];
        if (seg == 0) {
            int g = 0; float bv = x[3];
            if (x[4] > bv) { bv = x[4]; g = 1; }
            if (x[5] > bv) { bv = x[5]; g = 2; }
            if (x[6] > bv) { bv = x[6]; g = 3; }
            g_gid[b * NPTS + pbase + pt] = (unsigned char)g;
        }
#pragma unroll 4
        for (int kp = seg * 16; kp < seg * 16 + 16; kp++) {
            const int c = 2 * kp;
            const float* w0 = stage + c * 7;
            const float* w1 = w0 + 7;
            float s0 = stage[448 + c], s1 = stage[448 + c + 1];
#pragma unroll
            for (int k = 0; k < INC; k++) { s0 = fmaf(w0[k], x[k], s0); s1 = fmaf(w1[k], x[k], s1); }
            u32 hi, lo;
            split_pair(fmaxf(s0, 0.0f), fmaxf(s1, 0.0f), hi, lo);
            actA[kp * AST + pt] = hi;
            actA[ACT_PL + kp * AST + pt] = lo;
        }
    }
    CP_WAIT0();
    __syncthreads();

    cpw(sbase + OFF_WBB * 4, g_w2hi, g_w2lo, 64, tid);
    CP_COMMIT();

    layer_mma<1>(wbufA, 64 * WST, actA, stage, bl1, tid);
    __syncthreads();
    {
        const int pt = tid & 127, seg = tid >> 7;
#pragma unroll 4
        for (int kp = seg * 16; kp < seg * 16 + 16; kp++) {
            u32 hi, lo;
            split_pair(stage[(2 * kp) * 130 + pt], stage[(2 * kp + 1) * 130 + pt], hi, lo);
            actB[kp * AST + pt] = hi;
            actB[ACT_PL + kp * AST + pt] = lo;
        }
    }
    cpw(sbase + OFF_WBA * 4, g_w3hi, g_w3lo, 128, tid);
    CP_COMMIT();
    CP_WAIT1();
    __syncthreads();

    layer_mma<1>(wbufB, 64 * WST, actB, stage, bl2, tid);
    __syncthreads();
    {
        const int pt = tid & 127, seg = tid >> 7;
#pragma unroll 4
        for (int kp = seg * 16; kp < seg * 16 + 16; kp++) {
            u32 hi, lo;
            split_pair(stage[(2 * kp) * 130 + pt], stage[(2 * kp + 1) * 130 + pt], hi, lo);
            actA[kp * AST + pt] = hi;
            actA[ACT_PL + kp * AST + pt] = lo;
        }
    }
    CP_WAIT0();
    __syncthreads();

    layer_mma<2>(wbufA, 128 * WST, actA, stage, bl3, tid);
    __syncthreads();
    {
        const int pt = tid & 127, seg = tid >> 7;
#pragma unroll 4
        for (int kp = seg * 32; kp < seg * 32 + 32; kp++) {
            u32 hi, lo;
            split_pair(stage[(2 * kp) * 130 + pt], stage[(2 * kp + 1) * 130 + pt], hi, lo);
            g_hhi[((size_t)b * 64 + kp) * NPTS + pbase + pt] = hi;
            g_hlo[((size_t)b * 64 + kp) * NPTS + pbase + pt] = lo;
        }
    }
}

// ================= kernel B: R13 proven (register-running u64 keys, channel-outer epilogue) =================
#define WS2 68
#define HS2 136
#define KB_W_U (2 * 128 * WS2)
#define KB_H_U (2 * 64 * HS2)
#define KB_SMEM_BYTES ((KB_W_U + 2 * KB_H_U) * 4)

__global__ __launch_bounds__(256, 1)
void kB(const float* __restrict__ bl4) {
    extern __shared__ float smf[];
    u32* swp = reinterpret_cast<u32*>(smf);
    u32* hbuf0 = swp + KB_W_U;
    u32* hbuf1 = hbuf0 + KB_H_U;
    __shared__ unsigned char gid_s[128];

    const int tid = threadIdx.x;
    const int bid = blockIdx.x;
    const int b  = bid >> 6;
    const int pg = (bid >> 3) & 7;
    const int cc = bid & 7;
    const int c0 = cc * 128;

#pragma unroll
    for (int j = 0; j < 8; j++) {
        int idx = j * 256 + tid;
        int r = idx >> 4, q = (idx & 15) * 4;
        uint4 vh = *reinterpret_cast<const uint4*>(g_wphi + (size_t)(c0 + r) * 64 + q);
        uint4 vl = *reinterpret_cast<const uint4*>(g_wplo + (size_t)(c0 + r) * 64 + q);
        *reinterpret_cast<uint4*>(&swp[r * WS2 + q]) = vh;
        *reinterpret_cast<uint4*>(&swp[128 * WS2 + r * WS2 + q]) = vl;
    }

    const u32 hadd[2] = { smem_u32(hbuf0), smem_u32(hbuf1) };
    {
        const int pbase = pg * 2048;
#pragma unroll
        for (int j = 0; j < 16; j++) {
            int idx = j * 256 + tid;
            int row = idx >> 5, q = (idx & 31) * 4;
            const u32* src = (row < 64)
                ? g_hhi + ((size_t)b * 64 + row) * NPTS + pbase + q
                : g_hlo + ((size_t)b * 64 + (row - 64)) * NPTS + pbase + q;
            CP_ASYNC16(hadd[0] + (u32)(row * HS2 + q) * 4, src);
        }
        CP_COMMIT();
    }

    const int lane = tid & 31, wrp = tid >> 5;
    const int mw = wrp >> 1;
    const int nw = wrp & 1;
    const int gid4 = lane >> 2, tig = lane & 3;
    const int cw = mw * 32, pw = nw * 64;

    float biasr[2][2];
    u64 pk[2][2];
    float gm[2][2][4];
#pragma unroll
    for (int mt = 0; mt < 2; mt++)
#pragma unroll
        for (int hf = 0; hf < 2; hf++) {
            biasr[mt][hf] = __ldg(&bl4[c0 + cw + mt * 16 + gid4 + hf * 8]);
            pk[mt][hf] = 0ull;
#pragma unroll
            for (int g = 0; g < 4; g++) gm[mt][hf][g] = 0.0f;
        }

#pragma unroll 1
    for (int t = 0; t < 16; t++) {
        const int pbase = (pg * 16 + t) * 128;
        u32* shp = (t & 1) ? hbuf1 : hbuf0;
        if (t + 1 < 16) {
            const int pn = (pg * 16 + t + 1) * 128;
            const u32 dsta = hadd[(t + 1) & 1];
#pragma unroll
            for (int j = 0; j < 16; j++) {
                int idx = j * 256 + tid;
                int row = idx >> 5, q = (idx & 31) * 4;
                const u32* src = (row < 64)
                    ? g_hhi + ((size_t)b * 64 + row) * NPTS + pn + q
                    : g_hlo + ((size_t)b * 64 + (row - 64)) * NPTS + pn + q;
                CP_ASYNC16(dsta + (u32)(row * HS2 + q) * 4, src);
            }
            CP_COMMIT();
            CP_WAIT1();
        } else {
            CP_WAIT0();
        }
        if (tid < 128) gid_s[tid] = g_gid[b * NPTS + pbase + tid];
        __syncthreads();

        float acc[2][8][4];
#pragma unroll
        for (int mt = 0; mt < 2; mt++)
#pragma unroll
            for (int nt = 0; nt < 8; nt++)
#pragma unroll
                for (int j = 0; j < 4; j++) acc[mt][nt][j] = 0.0f;

        const u32* swhi = swp;
        const u32* swlo = swp + 128 * WS2;
        const u32* shhi = shp;
        const u32* shlo = shp + 64 * HS2;

#pragma unroll 1
        for (int kk = 0; kk < 8; kk++) {
            const int kpb = kk * 8;
            u32 ahi[2][4], alo[2][4];
#pragma unroll
            for (int mt = 0; mt < 2; mt++) {
                const int r0 = cw + mt * 16 + gid4;
#pragma unroll
                for (int q = 0; q < 4; q++) {
                    const int rr = r0 + (q & 1) * 8;
                    const int kq = kpb + tig + (q >> 1) * 4;
                    ahi[mt][q] = swhi[rr * WS2 + kq];
                    alo[mt][q] = swlo[rr * WS2 + kq];
                }
            }
            u32 bhi[8][2], blo[8][2];
#pragma unroll
            for (int nt = 0; nt < 8; nt++) {
                const int pp = pw + nt * 8 + gid4;
#pragma unroll
                for (int q = 0; q < 2; q++) {
                    const int kr = kpb + tig + q * 4;
                    bhi[nt][q] = shhi[kr * HS2 + pp];
                    blo[nt][q] = shlo[kr * HS2 + pp];
                }
            }
#pragma unroll
            for (int mt = 0; mt < 2; mt++)
#pragma unroll
                for (int nt = 0; nt < 8; nt++) {
                    mma16(acc[mt][nt], ahi[mt], bhi[nt]);
                    mma16(acc[mt][nt], ahi[mt], blo[nt]);
                    mma16(acc[mt][nt], alo[mt], bhi[nt]);
                }
        }

#pragma unroll
        for (int mt = 0; mt < 2; mt++)
#pragma unroll
            for (int hf = 0; hf < 2; hf++) {
                const float bias_c = biasr[mt][hf];
                u64 key = pk[mt][hf];
                float g0 = gm[mt][hf][0], g1 = gm[mt][hf][1];
                float g2 = gm[mt][hf][2], g3 = gm[mt][hf][3];
#pragma unroll
                for (int nt = 0; nt < 8; nt++)
#pragma unroll
                    for (int jj = 0; jj < 2; jj++) {
                        float val = fmaxf(fmaf(acc[mt][nt][hf * 2 + jj], 0.015625f, bias_c), 0.0f);
                        const int pl = pw + nt * 8 + tig * 2 + jj;
                        u64 k = ((u64)__float_as_uint(val) << 32) |
                                (u64)(0xFFFFFFFFu - (u32)(pbase + pl));
                        if (k > key) key = k;
                        const int gi = gid_s[pl];
                        g0 = fmaxf(g0, gi == 0 ? val : 0.f);
                        g1 = fmaxf(g1, gi == 1 ? val : 0.f);
                        g2 = fmaxf(g2, gi == 2 ? val : 0.f);
                        g3 = fmaxf(g3, gi == 3 ? val : 0.f);
                    }
                pk[mt][hf] = key;
                gm[mt][hf][0] = g0; gm[mt][hf][1] = g1;
                gm[mt][hf][2] = g2; gm[mt][hf][3] = g3;
            }
        __syncthreads();
    }

    u64* skey = reinterpret_cast<u64*>(hbuf0);
    float* sg = reinterpret_cast<float*>(skey + 1024);
    const int slot = nw * 4 + tig;
#pragma unroll
    for (int mt = 0; mt < 2; mt++)
#pragma unroll
        for (int hf = 0; hf < 2; hf++) {
            const int c = cw + mt * 16 + gid4 + hf * 8;
            skey[c * 8 + slot] = pk[mt][hf];
#pragma unroll
            for (int g = 0; g < 4; g++) sg[(c * 8 + slot) * 4 + g] = gm[mt][hf][g];
        }
    __syncthreads();

    if (tid < 128) {
        const int c = tid;
        u64 m = skey[c * 8];
        float mg[4] = { sg[c * 32 + 0], sg[c * 32 + 1], sg[c * 32 + 2], sg[c * 32 + 3] };
#pragma unroll
        for (int q = 1; q < 8; q++) {
            u64 e = skey[c * 8 + q];
            if (e > m) m = e;
#pragma unroll
            for (int g = 0; g < 4; g++) mg[g] = fmaxf(mg[g], sg[(c * 8 + q) * 4 + g]);
        }
        atomicMax(&g_pmax[b * 1024 + c0 + c], m);
#pragma unroll
        for (int g = 0; g < 4; g++)
            atomicMax(&g_gmax[g * 1024 + c0 + c], __float_as_uint(mg[g]));
    }
}

// ---------------- tail MLPs (unchanged) ----------------
__global__ void kC1(const float* __restrict__ wg0, const float* __restrict__ bg0,
                    const float* __restrict__ wgr0, const float* __restrict__ bgr0,
                    float* __restrict__ out) {
    const int gtid = blockIdx.x * blockDim.x + threadIdx.x;
    if (gtid < BATCH * 1024) {
        unsigned long long pv = g_pmax[gtid];
        out[4096 + gtid] = (float)(0xFFFFFFFFu - (unsigned int)(pv & 0xFFFFFFFFull));
    }
    const int wid = gtid >> 5;
    const int lane = gtid & 31;
    const int row = wid >> 9;
    const int j = wid & 511;
    if (row > 16) return;
    float s = 0.0f;
    if (row < 16) {
        const float* wr = wg0 + (size_t)j * 1024;
        const unsigned long long* pbuf = g_pmax + row * 1024;
        for (int k = lane; k < 1024; k += 32)
            s = fmaf(wr[k], __uint_as_float((unsigned int)(pbuf[k] >> 32)), s);
    } else {
        const float* wr = wgr0 + (size_t)j * 4096;
        for (int k = lane; k < 4096; k += 32)
            s = fmaf(wr[k], __uint_as_float(g_gmax[k]), s);
    }
#pragma unroll
    for (int o = 16; o; o >>= 1) s += __shfl_xor_sync(0xFFFFFFFFu, s, o);
    if (lane == 0) {
        float bb = (row < 16) ? bg0[j] : bgr0[j];
        g_u1[row * 512 + j] = fmaxf(s + bb, 0.0f);
    }
}

__global__ void kC2(const float* __restrict__ wg1, const float* __restrict__ bg1,
                    const float* __restrict__ wgr1, const float* __restrict__ bgr1,
                    float* __restrict__ out) {
    const int gtid = blockIdx.x * blockDim.x + threadIdx.x;
    const int wid = gtid >> 5;
    const int lane = gtid & 31;
    const int row = wid >> 7;
    const int j = wid & 127;
    if (row > 16) return;
    const float* wr = ((row < 16) ? wg1 : wgr1) + (size_t)j * 512;
    const float* in = g_u1 + row * 512;
    float s = 0.0f;
    for (int k = lane; k < 512; k += 32) s = fmaf(wr[k], in[k], s);
#pragma unroll
    for (int o = 16; o; o >>= 1) s += __shfl_xor_sync(0xFFFFFFFFu, s, o);
    s = __shfl_sync(0xFFFFFFFFu, s, 0);
    float bb = (row < 16) ? bg1[j] : bgr1[j];
    float val = fmaxf(s + bb, 0.0f);
    if (row < 16) {
        if (lane == 0) out[row * 256 + 128 + j] = val;
    } else {
        if (lane < 16) out[lane * 256 + j] = val;
    }
}

// ---------------- launch ----------------
extern "C" void kernel_launch(void* const* d_in, const int* in_sizes, int n_in,
                              void* d_out, int out_size) {
    const float* points = (const float*)d_in[0];
    const float* wl0 = (const float*)d_in[1];  const float* bl0 = (const float*)d_in[2];
    const float* wl1 = (const float*)d_in[3];  const float* bl1 = (const float*)d_in[4];
    const float* wl2 = (const float*)d_in[5];  const float* bl2 = (const float*)d_in[6];
    const float* wl3 = (const float*)d_in[7];  const float* bl3 = (const float*)d_in[8];
    const float* wl4 = (const float*)d_in[9];  const float* bl4 = (const float*)d_in[10];
    const float* wg0 = (const float*)d_in[11]; const float* bg0 = (const float*)d_in[12];
    const float* wg1 = (const float*)d_in[13]; const float* bg1 = (const float*)d_in[14];
    const float* wgr0 = (const float*)d_in[15]; const float* bgr0 = (const float*)d_in[16];
    const float* wgr1 = (const float*)d_in[17]; const float* bgr1 = (const float*)d_in[18];
    float* out = (float*)d_out;

    cudaFuncSetAttribute(kA, cudaFuncAttributeMaxDynamicSharedMemorySize,
                         KA_SMEM_U32 * (int)sizeof(u32));
    cudaFuncSetAttribute(kB, cudaFuncAttributeMaxDynamicSharedMemorySize, KB_SMEM_BYTES);

    kWall<<<288, 256>>>(wl1, wl2, wl3, wl4);
    kA<<<BATCH * NPTS / 128, 256, KA_SMEM_U32 * sizeof(u32)>>>(
        points, wl0, bl0, bl1, bl2, bl3);
    kB<<<1024, 256, KB_SMEM_BYTES>>>(bl4);
    kC1<<<1088, 256>>>(wg0, bg0, wgr0, bgr0, out);
    kC2<<<272, 256>>>(wg1, bg1, wgr1, bgr1, out);
}

// round 16
// speedup vs baseline: 1.6081x; 1.0314x over previous
#include <cuda_runtime.h>
#include <cuda_fp16.h>
#include <cstdint>

#define NPTS 16384
#define BATCH 16
#define INC 7
typedef unsigned long long u64;
typedef unsigned int u32;

// ---------------- scratch ----------------
__device__ u32                g_hhi[(size_t)BATCH * 64 * NPTS]; // (b, kp, i)
__device__ u32                g_hlo[(size_t)BATCH * 64 * NPTS];
__device__ u32                g_wphi[1024 * 64];                // W4 (c, kp), x64
__device__ u32                g_wplo[1024 * 64];
__device__ u32                g_w1hi[64 * 32],  g_w1lo[64 * 32];   // W1 x64
__device__ u32                g_w2hi[64 * 32],  g_w2lo[64 * 32];   // W2 x64
__device__ u32                g_w3hi[128 * 32], g_w3lo[128 * 32];  // W3 x64
__device__ unsigned char      g_gid[BATCH * NPTS];
__device__ unsigned long long g_pmax[BATCH * 1024];
__device__ unsigned int       g_gmax[4 * 1024];
__device__ float              g_u1[17 * 512];

__device__ __forceinline__ void split_limbs(float v, unsigned short& hi, unsigned short& lo) {
    __half h = __float2half_rn(v);
    float r = v - __half2float(h);
    __half l = __float2half_rn(r);
    hi = __half_as_ushort(h);
    lo = __half_as_ushort(l);
}
__device__ __forceinline__ void split_pair(float a, float b, u32& hi, u32& lo) {
    unsigned short h0, l0, h1, l1;
    split_limbs(a, h0, l0); split_limbs(b, h1, l1);
    hi = (u32)h0 | ((u32)h1 << 16);
    lo = (u32)l0 | ((u32)l1 << 16);
}
__device__ __forceinline__ void mma16(float* d, const u32* a, const u32* b) {
    asm volatile("mma.sync.aligned.m16n8k16.row.col.f32.f16.f16.f32 "
                 "{%0,%1,%2,%3}, {%4,%5,%6,%7}, {%8,%9}, {%0,%1,%2,%3};"
                 : "+f"(d[0]), "+f"(d[1]), "+f"(d[2]), "+f"(d[3])
                 : "r"(a[0]), "r"(a[1]), "r"(a[2]), "r"(a[3]), "r"(b[0]), "r"(b[1]));
}
__device__ __forceinline__ u32 smem_u32(const void* p) {
    u32 a; asm("{ .reg .u64 t; cvta.to.shared.u64 t, %1; cvt.u32.u64 %0, t; }" : "=r"(a) : "l"(p)); return a;
}
#define CP_ASYNC16(dst, src) asm volatile("cp.async.cg.shared.global [%0], [%1], 16;" :: "r"(dst), "l"(src) : "memory")
#define CP_COMMIT()  asm volatile("cp.async.commit_group;" ::: "memory")
#define CP_WAIT0()   asm volatile("cp.async.wait_group 0;" ::: "memory")
#define CP_WAIT1()   asm volatile("cp.async.wait_group 1;" ::: "memory")

// ================= kernel Wall: weight limb-split + reduction-buffer init =================
__global__ void kWall(const float* __restrict__ wl1, const float* __restrict__ wl2,
                      const float* __restrict__ wl3, const float* __restrict__ wl4) {
    int T = blockIdx.x * blockDim.x + threadIdx.x;
    if (T < BATCH * 1024) g_pmax[T] = 0ull;
    if (T < 4 * 1024) g_gmax[T] = 0u;
    const float* src; u32 *dhi, *dlo; int c, kp, K;
    if (T < 2048)       { src = wl1; dhi = g_w1hi; dlo = g_w1lo; int t = T;          c = t >> 5; kp = t & 31; K = 64;  dhi += t; dlo += t; }
    else if (T < 4096)  { src = wl2; dhi = g_w2hi; dlo = g_w2lo; int t = T - 2048;   c = t >> 5; kp = t & 31; K = 64;  dhi += t; dlo += t; }
    else if (T < 8192)  { src = wl3; dhi = g_w3hi; dlo = g_w3lo; int t = T - 4096;   c = t >> 5; kp = t & 31; K = 64;  dhi += t; dlo += t; }
    else if (T < 73728) { src = wl4; dhi = g_wphi; dlo = g_wplo; int t = T - 8192;   c = t >> 6; kp = t & 63; K = 128; dhi += t; dlo += t; }
    else return;
    u32 hi, lo;
    split_pair(src[c * K + 2 * kp] * 64.0f, src[c * K + 2 * kp + 1] * 64.0f, hi, lo);
    *dhi = hi; *dlo = lo;
}

// ================= kernel A: L0 scalar + L1/L2/L3 split-fp16 MMA, direct limb epilogue =================
#define OFF_WBA 0
#define OFF_WBB 9216
#define OFF_ACTA 13824
#define OFF_ACTB 22528
#define OFF_STAGE 31232
#define KA_SMEM_U32 47872
#define ACT_PL 4352
#define AST 136
#define WST 36

__device__ __forceinline__ void cpw(u32 dst, const u32* hi, const u32* lo, int C, int tid) {
    const int chunks = C * 8;
    for (int j = tid; j < 2 * chunks; j += 256) {
        int plane = (j >= chunks);
        int r = (j - plane * chunks) >> 3;
        int q = (j & 7) * 4;
        const u32* src = (plane ? lo : hi) + r * 32 + q;
        CP_ASYNC16(dst + (u32)(plane * C * WST + r * WST + q) * 4, src);
    }
}

// L1/L2: mainloop + direct limb write into next act buffer (bit-identical to stage roundtrip)
__device__ __forceinline__ void layer_mma_act(const u32* __restrict__ wb, int wplane,
                                              const u32* __restrict__ actin,
                                              u32* __restrict__ actout,
                                              const float* __restrict__ bias, int tid) {
    const int lane = tid & 31, wrp = tid >> 5;
    const int mw = wrp >> 1, nw = wrp & 1;
    const int gid4 = lane >> 2, tig = lane & 3;
    const int cw = mw * 16, pw = nw * 64;

    float acc[8][4];
#pragma unroll
    for (int nt = 0; nt < 8; nt++)
#pragma unroll
        for (int j = 0; j < 4; j++) acc[nt][j] = 0.0f;

#pragma unroll
    for (int kk = 0; kk < 4; kk++) {
        const int kpb = kk * 8;
        u32 ahi[4], alo[4];
        const int r0 = cw + gid4;
#pragma unroll
        for (int q = 0; q < 4; q++) {
            const int rr = r0 + (q & 1) * 8;
            const int kq = kpb + tig + (q >> 1) * 4;
            ahi[q] = wb[rr * WST + kq];
            alo[q] = wb[wplane + rr * WST + kq];
        }
        u32 bhi[8][2], blo[8][2];
#pragma unroll
        for (int nt = 0; nt < 8; nt++) {
            const int pp = pw + nt * 8 + gid4;
#pragma unroll
            for (int q = 0; q < 2; q++) {
                const int kr = kpb + tig + q * 4;
                bhi[nt][q] = actin[kr * AST + pp];
                blo[nt][q] = actin[ACT_PL + kr * AST + pp];
            }
        }
#pragma unroll
        for (int nt = 0; nt < 8; nt++) {
            mma16(acc[nt], ahi, bhi[nt]);
            mma16(acc[nt], ahi, blo[nt]);
            mma16(acc[nt], alo, bhi[nt]);
        }
    }
    // direct limb epilogue: channel-outer order (load-bearing, do not invert)
    char* outc = reinterpret_cast<char*>(actout);
#pragma unroll
    for (int hf = 0; hf < 2; hf++) {
        const int c = cw + gid4 + hf * 8;
        const float bias_c = __ldg(&bias[c]);
        const int half_off = (c & 1) * 2;
        const int kp_base = (c >> 1) * AST;
#pragma unroll
        for (int nt = 0; nt < 8; nt++)
#pragma unroll
            for (int jj = 0; jj < 2; jj++) {
                float val = fmaxf(fmaf(acc[nt][hf * 2 + jj], 0.015625f, bias_c), 0.0f);
                unsigned short hi, lo;
                split_limbs(val, hi, lo);
                const int pl = pw + nt * 8 + tig * 2 + jj;
                char* base = outc + (u32)((kp_base + pl) * 4 + half_off);
                *reinterpret_cast<unsigned short*>(base) = hi;
                *reinterpret_cast<unsigned short*>(base + ACT_PL * 4) = lo;
            }
    }
}

// L3: mainloop (MT=2) + fp32 stage write (kept for coalesced global store)
__device__ __forceinline__ void layer_mma_stage(const u32* __restrict__ wb, int wplane,
                                                const u32* __restrict__ act,
                                                float* __restrict__ stage,
                                                const float* __restrict__ bias, int tid) {
    const int lane = tid & 31, wrp = tid >> 5;
    const int mw = wrp >> 1, nw = wrp & 1;
    const int gid4 = lane >> 2, tig = lane & 3;
    const int cw = mw * 32, pw = nw * 64;

    float acc[2][8][4];
#pragma unroll
    for (int mt = 0; mt < 2; mt++)
#pragma unroll
        for (int nt = 0; nt < 8; nt++)
#pragma unroll
            for (int j = 0; j < 4; j++) acc[mt][nt][j] = 0.0f;

#pragma unroll
    for (int kk = 0; kk < 4; kk++) {
        const int kpb = kk * 8;
        u32 ahi[2][4], alo[2][4];
#pragma unroll
        for (int mt = 0; mt < 2; mt++) {
            const int r0 = cw + mt * 16 + gid4;
#pragma unroll
            for (int q = 0; q < 4; q++) {
                const int rr = r0 + (q & 1) * 8;
                const int kq = kpb + tig + (q >> 1) * 4;
                ahi[mt][q] = wb[rr * WST + kq];
                alo[mt][q] = wb[wplane + rr * WST + kq];
            }
        }
        u32 bhi[8][2], blo[8][2];
#pragma unroll
        for (int nt = 0; nt < 8; nt++) {
            const int pp = pw + nt * 8 + gid4;
#pragma unroll
            for (int q = 0; q < 2; q++) {
                const int kr = kpb + tig + q * 4;
                bhi[nt][q] = act[kr * AST + pp];
                blo[nt][q] = act[ACT_PL + kr * AST + pp];
            }
        }
#pragma unroll
        for (int mt = 0; mt < 2; mt++)
#pragma unroll
            for (int nt = 0; nt < 8; nt++) {
                mma16(acc[mt][nt], ahi[mt], bhi[nt]);
                mma16(acc[mt][nt], ahi[mt], blo[nt]);
                mma16(acc[mt][nt], alo[mt], bhi[nt]);
            }
    }
#pragma unroll
    for (int mt = 0; mt < 2; mt++)
#pragma unroll
        for (int hf = 0; hf < 2; hf++) {
            const int c = cw + mt * 16 + gid4 + hf * 8;
            const float bias_c = __ldg(&bias[c]);
#pragma unroll
            for (int nt = 0; nt < 8; nt++)
#pragma unroll
                for (int jj = 0; jj < 2; jj++) {
                    float val = fmaxf(fmaf(acc[mt][nt][hf * 2 + jj], 0.015625f, bias_c), 0.0f);
                    stage[c * 130 + pw + nt * 8 + tig * 2 + jj] = val;
                }
        }
}

__global__ __launch_bounds__(256, 1)
void kA(const float* __restrict__ points,
        const float* __restrict__ wl0, const float* __restrict__ bl0,
        const float* __restrict__ bl1, const float* __restrict__ bl2,
        const float* __restrict__ bl3) {
    extern __shared__ u32 smu[];
    u32* wbufA = smu + OFF_WBA;
    u32* wbufB = smu + OFF_WBB;
    u32* actA  = smu + OFF_ACTA;
    u32* actB  = smu + OFF_ACTB;
    float* stage = reinterpret_cast<float*>(smu + OFF_STAGE);
    const u32 sbase = smem_u32(smu);
    const int tid = threadIdx.x;
    const int bid = blockIdx.x;
    const int b = bid >> 7;
    const int pbase = (bid & 127) * 128;

    cpw(sbase + OFF_WBA * 4, g_w1hi, g_w1lo, 64, tid);
    CP_COMMIT();

    for (int i = tid; i < 448; i += 256) stage[i] = wl0[i];
    for (int i = tid; i < 64; i += 256) stage[448 + i] = bl0[i];
    __syncthreads();

    // L0: 7 -> 64 scalar, direct limb act tile
    {
        const int pt = tid & 127, seg = tid >> 7;
        const float* ptp = points + (size_t)b * INC * NPTS + pbase + pt;
        float x[INC];
#pragma unroll
        for (int c = 0; c < INC; c++) x[c] = ptp[(size_t)c * NPTS];
        if (seg == 0) {
            int g = 0; float bv = x[3];
            if (x[4] > bv) { bv = x[4]; g = 1; }
            if (x[5] > bv) { bv = x[5]; g = 2; }
            if (x[6] > bv) { bv = x[6]; g = 3; }
            g_gid[b * NPTS + pbase + pt] = (unsigned char)g;
        }
#pragma unroll 4
        for (int kp = seg * 16; kp < seg * 16 + 16; kp++) {
            const int c = 2 * kp;
            const float* w0 = stage + c * 7;
            const float* w1 = w0 + 7;
            float s0 = stage[448 + c], s1 = stage[448 + c + 1];
#pragma unroll
            for (int k = 0; k < INC; k++) { s0 = fmaf(w0[k], x[k], s0); s1 = fmaf(w1[k], x[k], s1); }
            u32 hi, lo;
            split_pair(fmaxf(s0, 0.0f), fmaxf(s1, 0.0f), hi, lo);
            actA[kp * AST + pt] = hi;
            actA[ACT_PL + kp * AST + pt] = lo;
        }
    }
    CP_WAIT0();
    __syncthreads();                       // W1 + actA visible, stage(W0) reads done

    cpw(sbase + OFF_WBB * 4, g_w2hi, g_w2lo, 64, tid);
    CP_COMMIT();
    layer_mma_act(wbufA, 64 * WST, actA, actB, bl1, tid);   // L1 -> actB direct
    CP_WAIT0();
    __syncthreads();                       // W2 + actB visible

    cpw(sbase + OFF_WBA * 4, g_w3hi, g_w3lo, 128, tid);     // wbufA free (L1 done)
    CP_COMMIT();
    layer_mma_act(wbufB, 64 * WST, actB, actA, bl2, tid);   // L2 -> actA direct
    CP_WAIT0();
    __syncthreads();                       // W3 + actA visible

    layer_mma_stage(wbufA, 128 * WST, actA, stage, bl3, tid);   // L3 -> stage
    __syncthreads();
    {
        const int pt = tid & 127, seg = tid >> 7;
#pragma unroll 4
        for (int kp = seg * 32; kp < seg * 32 + 32; kp++) {
            u32 hi, lo;
            split_pair(stage[(2 * kp) * 130 + pt], stage[(2 * kp + 1) * 130 + pt], hi, lo);
            g_hhi[((size_t)b * 64 + kp) * NPTS + pbase + pt] = hi;
            g_hlo[((size_t)b * 64 + kp) * NPTS + pbase + pt] = lo;
        }
    }
}

// ================= kernel B: R13/R15 proven — DO NOT MODIFY =================
#define WS2 68
#define HS2 136
#define KB_W_U (2 * 128 * WS2)
#define KB_H_U (2 * 64 * HS2)
#define KB_SMEM_BYTES ((KB_W_U + 2 * KB_H_U) * 4)

__global__ __launch_bounds__(256, 1)
void kB(const float* __restrict__ bl4) {
    extern __shared__ float smf[];
    u32* swp = reinterpret_cast<u32*>(smf);
    u32* hbuf0 = swp + KB_W_U;
    u32* hbuf1 = hbuf0 + KB_H_U;
    __shared__ unsigned char gid_s[128];

    const int tid = threadIdx.x;
    const int bid = blockIdx.x;
    const int b  = bid >> 6;
    const int pg = (bid >> 3) & 7;
    const int cc = bid & 7;
    const int c0 = cc * 128;

#pragma unroll
    for (int j = 0; j < 8; j++) {
        int idx = j * 256 + tid;
        int r = idx >> 4, q = (idx & 15) * 4;
        uint4 vh = *reinterpret_cast<const uint4*>(g_wphi + (size_t)(c0 + r) * 64 + q);
        uint4 vl = *reinterpret_cast<const uint4*>(g_wplo + (size_t)(c0 + r) * 64 + q);
        *reinterpret_cast<uint4*>(&swp[r * WS2 + q]) = vh;
        *reinterpret_cast<uint4*>(&swp[128 * WS2 + r * WS2 + q]) = vl;
    }

    const u32 hadd[2] = { smem_u32(hbuf0), smem_u32(hbuf1) };
    {
        const int pbase = pg * 2048;
#pragma unroll
        for (int j = 0; j < 16; j++) {
            int idx = j * 256 + tid;
            int row = idx >> 5, q = (idx & 31) * 4;
            const u32* src = (row < 64)
                ? g_hhi + ((size_t)b * 64 + row) * NPTS + pbase + q
                : g_hlo + ((size_t)b * 64 + (row - 64)) * NPTS + pbase + q;
            CP_ASYNC16(hadd[0] + (u32)(row * HS2 + q) * 4, src);
        }
        CP_COMMIT();
    }

    const int lane = tid & 31, wrp = tid >> 5;
    const int mw = wrp >> 1;
    const int nw = wrp & 1;
    const int gid4 = lane >> 2, tig = lane & 3;
    const int cw = mw * 32, pw = nw * 64;

    float biasr[2][2];
    u64 pk[2][2];
    float gm[2][2][4];
#pragma unroll
    for (int mt = 0; mt < 2; mt++)
#pragma unroll
        for (int hf = 0; hf < 2; hf++) {
            biasr[mt][hf] = __ldg(&bl4[c0 + cw + mt * 16 + gid4 + hf * 8]);
            pk[mt][hf] = 0ull;
#pragma unroll
            for (int g = 0; g < 4; g++) gm[mt][hf][g] = 0.0f;
        }

#pragma unroll 1
    for (int t = 0; t < 16; t++) {
        const int pbase = (pg * 16 + t) * 128;
        u32* shp = (t & 1) ? hbuf1 : hbuf0;
        if (t + 1 < 16) {
            const int pn = (pg * 16 + t + 1) * 128;
            const u32 dsta = hadd[(t + 1) & 1];
#pragma unroll
            for (int j = 0; j < 16; j++) {
                int idx = j * 256 + tid;
                int row = idx >> 5, q = (idx & 31) * 4;
                const u32* src = (row < 64)
                    ? g_hhi + ((size_t)b * 64 + row) * NPTS + pn + q
                    : g_hlo + ((size_t)b * 64 + (row - 64)) * NPTS + pn + q;
                CP_ASYNC16(dsta + (u32)(row * HS2 + q) * 4, src);
            }
            CP_COMMIT();
            CP_WAIT1();
        } else {
            CP_WAIT0();
        }
        if (tid < 128) gid_s[tid] = g_gid[b * NPTS + pbase + tid];
        __syncthreads();

        float acc[2][8][4];
#pragma unroll
        for (int mt = 0; mt < 2; mt++)
#pragma unroll
            for (int nt = 0; nt < 8; nt++)
#pragma unroll
                for (int j = 0; j < 4; j++) acc[mt][nt][j] = 0.0f;

        const u32* swhi = swp;
        const u32* swlo = swp + 128 * WS2;
        const u32* shhi = shp;
        const u32* shlo = shp + 64 * HS2;

#pragma unroll 1
        for (int kk = 0; kk < 8; kk++) {
            const int kpb = kk * 8;
            u32 ahi[2][4], alo[2][4];
#pragma unroll
            for (int mt = 0; mt < 2; mt++) {
                const int r0 = cw + mt * 16 + gid4;
#pragma unroll
                for (int q = 0; q < 4; q++) {
                    const int rr = r0 + (q & 1) * 8;
                    const int kq = kpb + tig + (q >> 1) * 4;
                    ahi[mt][q] = swhi[rr * WS2 + kq];
                    alo[mt][q] = swlo[rr * WS2 + kq];
                }
            }
            u32 bhi[8][2], blo[8][2];
#pragma unroll
            for (int nt = 0; nt < 8; nt++) {
                const int pp = pw + nt * 8 + gid4;
#pragma unroll
                for (int q = 0; q < 2; q++) {
                    const int kr = kpb + tig + q * 4;
                    bhi[nt][q] = shhi[kr * HS2 + pp];
                    blo[nt][q] = shlo[kr * HS2 + pp];
                }
            }
#pragma unroll
            for (int mt = 0; mt < 2; mt++)
#pragma unroll
                for (int nt = 0; nt < 8; nt++) {
                    mma16(acc[mt][nt], ahi[mt], bhi[nt]);
                    mma16(acc[mt][nt], ahi[mt], blo[nt]);
                    mma16(acc[mt][nt], alo[mt], bhi[nt]);
                }
        }

#pragma unroll
        for (int mt = 0; mt < 2; mt++)
#pragma unroll
            for (int hf = 0; hf < 2; hf++) {
                const float bias_c = biasr[mt][hf];
                u64 key = pk[mt][hf];
                float g0 = gm[mt][hf][0], g1 = gm[mt][hf][1];
                float g2 = gm[mt][hf][2], g3 = gm[mt][hf][3];
#pragma unroll
                for (int nt = 0; nt < 8; nt++)
#pragma unroll
                    for (int jj = 0; jj < 2; jj++) {
                        float val = fmaxf(fmaf(acc[mt][nt][hf * 2 + jj], 0.015625f, bias_c), 0.0f);
                        const int pl = pw + nt * 8 + tig * 2 + jj;
                        u64 k = ((u64)__float_as_uint(val) << 32) |
                                (u64)(0xFFFFFFFFu - (u32)(pbase + pl));
                        if (k > key) key = k;
                        const int gi = gid_s[pl];
                        g0 = fmaxf(g0, gi == 0 ? val : 0.f);
                        g1 = fmaxf(g1, gi == 1 ? val : 0.f);
                        g2 = fmaxf(g2, gi == 2 ? val : 0.f);
                        g3 = fmaxf(g3, gi == 3 ? val : 0.f);
                    }
                pk[mt][hf] = key;
                gm[mt][hf][0] = g0; gm[mt][hf][1] = g1;
                gm[mt][hf][2] = g2; gm[mt][hf][3] = g3;
            }
        __syncthreads();
    }

    u64* skey = reinterpret_cast<u64*>(hbuf0);
    float* sg = reinterpret_cast<float*>(skey + 1024);
    const int slot = nw * 4 + tig;
#pragma unroll
    for (int mt = 0; mt < 2; mt++)
#pragma unroll
        for (int hf = 0; hf < 2; hf++) {
            const int c = cw + mt * 16 + gid4 + hf * 8;
            skey[c * 8 + slot] = pk[mt][hf];
#pragma unroll
            for (int g = 0; g < 4; g++) sg[(c * 8 + slot) * 4 + g] = gm[mt][hf][g];
        }
    __syncthreads();

    if (tid < 128) {
        const int c = tid;
        u64 m = skey[c * 8];
        float mg[4] = { sg[c * 32 + 0], sg[c * 32 + 1], sg[c * 32 + 2], sg[c * 32 + 3] };
#pragma unroll
        for (int q = 1; q < 8; q++) {
            u64 e = skey[c * 8 + q];
            if (e > m) m = e;
#pragma unroll
            for (int g = 0; g < 4; g++) mg[g] = fmaxf(mg[g], sg[(c * 8 + q) * 4 + g]);
        }
        atomicMax(&g_pmax[b * 1024 + c0 + c], m);
#pragma unroll
        for (int g = 0; g < 4; g++)
            atomicMax(&g_gmax[g * 1024 + c0 + c], __float_as_uint(mg[g]));
    }
}

// ---------------- tail MLPs (vectorized k-loops) ----------------
__global__ void kC1(const float* __restrict__ wg0, const float* __restrict__ bg0,
                    const float* __restrict__ wgr0, const float* __restrict__ bgr0,
                    float* __restrict__ out) {
    const int gtid = blockIdx.x * blockDim.x + threadIdx.x;
    if (gtid < BATCH * 1024) {
        unsigned long long pv = g_pmax[gtid];
        out[4096 + gtid] = (float)(0xFFFFFFFFu - (unsigned int)(pv & 0xFFFFFFFFull));
    }
    const int wid = gtid >> 5;
    const int lane = gtid & 31;
    const int row = wid >> 9;
    const int j = wid & 511;
    if (row > 16) return;
    float s = 0.0f;
    if (row < 16) {
        const float* wr = wg0 + (size_t)j * 1024;
        const unsigned long long* pbuf = g_pmax + row * 1024;
        for (int k = lane * 4; k < 1024; k += 128) {
            float4 w = *reinterpret_cast<const float4*>(wr + k);
            ulonglong2 p0 = *reinterpret_cast<const ulonglong2*>(pbuf + k);
            ulonglong2 p1 = *reinterpret_cast<const ulonglong2*>(pbuf + k + 2);
            s = fmaf(w.x, __uint_as_float((u32)(p0.x >> 32)), s);
            s = fmaf(w.y, __uint_as_float((u32)(p0.y >> 32)), s);
            s = fmaf(w.z, __uint_as_float((u32)(p1.x >> 32)), s);
            s = fmaf(w.w, __uint_as_float((u32)(p1.y >> 32)), s);
        }
    } else {
        const float* wr = wgr0 + (size_t)j * 4096;
        for (int k = lane * 4; k < 4096; k += 128) {
            float4 w = *reinterpret_cast<const float4*>(wr + k);
            uint4 gv = *reinterpret_cast<const uint4*>(g_gmax + k);
            s = fmaf(w.x, __uint_as_float(gv.x), s);
            s = fmaf(w.y, __uint_as_float(gv.y), s);
            s = fmaf(w.z, __uint_as_float(gv.z), s);
            s = fmaf(w.w, __uint_as_float(gv.w), s);
        }
    }
#pragma unroll
    for (int o = 16; o; o >>= 1) s += __shfl_xor_sync(0xFFFFFFFFu, s, o);
    if (lane == 0) {
        float bb = (row < 16) ? bg0[j] : bgr0[j];
        g_u1[row * 512 + j] = fmaxf(s + bb, 0.0f);
    }
}

__global__ void kC2(const float* __restrict__ wg1, const float* __restrict__ bg1,
                    const float* __restrict__ wgr1, const float* __restrict__ bgr1,
                    float* __restrict__ out) {
    const int gtid = blockIdx.x * blockDim.x + threadIdx.x;
    const int wid = gtid >> 5;
    const int lane = gtid & 31;
    const int row = wid >> 7;
    const int j = wid & 127;
    if (row > 16) return;
    const float* wr = ((row < 16) ? wg1 : wgr1) + (size_t)j * 512;
    const float* in = g_u1 + row * 512;
    float s = 0.0f;
    for (int k = lane * 4; k < 512; k += 128) {
        float4 w = *reinterpret_cast<const float4*>(wr + k);
        float4 v = *reinterpret_cast<const float4*>(in + k);
        s = fmaf(w.x, v.x, s);
        s = fmaf(w.y, v.y, s);
        s = fmaf(w.z, v.z, s);
        s = fmaf(w.w, v.w, s);
    }
#pragma unroll
    for (int o = 16; o; o >>= 1) s += __shfl_xor_sync(0xFFFFFFFFu, s, o);
    s = __shfl_sync(0xFFFFFFFFu, s, 0);
    float bb = (row < 16) ? bg1[j] : bgr1[j];
    float val = fmaxf(s + bb, 0.0f);
    if (row < 16) {
        if (lane == 0) out[row * 256 + 128 + j] = val;
    } else {
        if (lane < 16) out[lane * 256 + j] = val;
    }
}

// ---------------- launch ----------------
extern "C" void kernel_launch(void* const* d_in, const int* in_sizes, int n_in,
                              void* d_out, int out_size) {
    const float* points = (const float*)d_in[0];
    const float* wl0 = (const float*)d_in[1];  const float* bl0 = (const float*)d_in[2];
    const float* wl1 = (const float*)d_in[3];  const float* bl1 = (const float*)d_in[4];
    const float* wl2 = (const float*)d_in[5];  const float* bl2 = (const float*)d_in[6];
    const float* wl3 = (const float*)d_in[7];  const float* bl3 = (const float*)d_in[8];
    const float* wl4 = (const float*)d_in[9];  const float* bl4 = (const float*)d_in[10];
    const float* wg0 = (const float*)d_in[11]; const float* bg0 = (const float*)d_in[12];
    const float* wg1 = (const float*)d_in[13]; const float* bg1 = (const float*)d_in[14];
    const float* wgr0 = (const float*)d_in[15]; const float* bgr0 = (const float*)d_in[16];
    const float* wgr1 = (const float*)d_in[17]; const float* bgr1 = (const float*)d_in[18];
    float* out = (float*)d_out;

    cudaFuncSetAttribute(kA, cudaFuncAttributeMaxDynamicSharedMemorySize,
                         KA_SMEM_U32 * (int)sizeof(u32));
    cudaFuncSetAttribute(kB, cudaFuncAttributeMaxDynamicSharedMemorySize, KB_SMEM_BYTES);

    kWall<<<288, 256>>>(wl1, wl2, wl3, wl4);
    kA<<<BATCH * NPTS / 128, 256, KA_SMEM_U32 * sizeof(u32)>>>(
        points, wl0, bl0, bl1, bl2, bl3);
    kB<<<1024, 256, KB_SMEM_BYTES>>>(bl4);
    kC1<<<1088, 256>>>(wg0, bg0, wgr0, bgr0, out);
    kC2<<<272, 256>>>(wg1, bg1, wgr1, bgr1, out);
}

// round 17
// speedup vs baseline: 1.6115x; 1.0021x over previous
#include <cuda_runtime.h>
#include <cuda_fp16.h>
#include <cstdint>

#define NPTS 16384
#define BATCH 16
#define INC 7
typedef unsigned long long u64;
typedef unsigned int u32;

// ---------------- scratch ----------------
__device__ u32                g_hhi[(size_t)BATCH * 64 * NPTS]; // (b, kp, i)
__device__ u32                g_hlo[(size_t)BATCH * 64 * NPTS];
__device__ u32                g_wphi[1024 * 64];                // W4 (c, kp), x64
__device__ u32                g_wplo[1024 * 64];
__device__ u32                g_w1hi[64 * 32],  g_w1lo[64 * 32];   // W1 x64
__device__ u32                g_w2hi[64 * 32],  g_w2lo[64 * 32];   // W2 x64
__device__ u32                g_w3hi[128 * 32], g_w3lo[128 * 32];  // W3 x64
__device__ unsigned char      g_gid[BATCH * NPTS];
__device__ unsigned long long g_pmax[BATCH * 1024];
__device__ unsigned int       g_gmax[4 * 1024];
__device__ float              g_u1[17 * 512];

__device__ __forceinline__ void split_limbs(float v, unsigned short& hi, unsigned short& lo) {
    __half h = __float2half_rn(v);
    float r = v - __half2float(h);
    __half l = __float2half_rn(r);
    hi = __half_as_ushort(h);
    lo = __half_as_ushort(l);
}
__device__ __forceinline__ void split_pair(float a, float b, u32& hi, u32& lo) {
    unsigned short h0, l0, h1, l1;
    split_limbs(a, h0, l0); split_limbs(b, h1, l1);
    hi = (u32)h0 | ((u32)h1 << 16);
    lo = (u32)l0 | ((u32)l1 << 16);
}
__device__ __forceinline__ void mma16(float* d, const u32* a, const u32* b) {
    asm volatile("mma.sync.aligned.m16n8k16.row.col.f32.f16.f16.f32 "
                 "{%0,%1,%2,%3}, {%4,%5,%6,%7}, {%8,%9}, {%0,%1,%2,%3};"
                 : "+f"(d[0]), "+f"(d[1]), "+f"(d[2]), "+f"(d[3])
                 : "r"(a[0]), "r"(a[1]), "r"(a[2]), "r"(a[3]), "r"(b[0]), "r"(b[1]));
}
__device__ __forceinline__ u32 smem_u32(const void* p) {
    u32 a; asm("{ .reg .u64 t; cvta.to.shared.u64 t, %1; cvt.u32.u64 %0, t; }" : "=r"(a) : "l"(p)); return a;
}
#define CP_ASYNC16(dst, src) asm volatile("cp.async.cg.shared.global [%0], [%1], 16;" :: "r"(dst), "l"(src) : "memory")
#define CP_COMMIT()  asm volatile("cp.async.commit_group;" ::: "memory")
#define CP_WAIT0()   asm volatile("cp.async.wait_group 0;" ::: "memory")
#define CP_WAIT1()   asm volatile("cp.async.wait_group 1;" ::: "memory")

// ================= kernel Wall: weight limb-split + reduction-buffer init =================
__global__ void kWall(const float* __restrict__ wl1, const float* __restrict__ wl2,
                      const float* __restrict__ wl3, const float* __restrict__ wl4) {
    int T = blockIdx.x * blockDim.x + threadIdx.x;
    if (T < BATCH * 1024) g_pmax[T] = 0ull;
    if (T < 4 * 1024) g_gmax[T] = 0u;
    const float* src; u32 *dhi, *dlo; int c, kp, K;
    if (T < 2048)       { src = wl1; dhi = g_w1hi; dlo = g_w1lo; int t = T;          c = t >> 5; kp = t & 31; K = 64;  dhi += t; dlo += t; }
    else if (T < 4096)  { src = wl2; dhi = g_w2hi; dlo = g_w2lo; int t = T - 2048;   c = t >> 5; kp = t & 31; K = 64;  dhi += t; dlo += t; }
    else if (T < 8192)  { src = wl3; dhi = g_w3hi; dlo = g_w3lo; int t = T - 4096;   c = t >> 5; kp = t & 31; K = 64;  dhi += t; dlo += t; }
    else if (T < 73728) { src = wl4; dhi = g_wphi; dlo = g_wplo; int t = T - 8192;   c = t >> 6; kp = t & 63; K = 128; dhi += t; dlo += t; }
    else return;
    u32 hi, lo;
    split_pair(src[c * K + 2 * kp] * 64.0f, src[c * K + 2 * kp + 1] * 64.0f, hi, lo);
    *dhi = hi; *dlo = lo;
}

// ================= kernel A: 2 tiles/CTA, weights resident, direct limb epilogues =================
#define OFF_WBA 0          // W1: 4608 u32
#define OFF_WBB 4608       // W2: 4608 u32
#define OFF_WBC 9216       // W3: 9216 u32
#define OFF_ACTA 18432     // 8704 u32
#define OFF_ACTB 27136     // 8704 u32
#define OFF_STAGE 35840    // 16640 u32 (fp32 stage for L3)
#define OFF_W0 52480       // 512 u32 (W0+b0 fp32, never clobbered)
#define KA_SMEM_U32 52992
#define ACT_PL 4352
#define AST 136
#define WST 36

__device__ __forceinline__ void cpw(u32 dst, const u32* hi, const u32* lo, int C, int tid) {
    const int chunks = C * 8;
    for (int j = tid; j < 2 * chunks; j += 256) {
        int plane = (j >= chunks);
        int r = (j - plane * chunks) >> 3;
        int q = (j & 7) * 4;
        const u32* src = (plane ? lo : hi) + r * 32 + q;
        CP_ASYNC16(dst + (u32)(plane * C * WST + r * WST + q) * 4, src);
    }
}

// L1/L2: mainloop + direct limb write into next act buffer
__device__ __forceinline__ void layer_mma_act(const u32* __restrict__ wb, int wplane,
                                              const u32* __restrict__ actin,
                                              u32* __restrict__ actout,
                                              const float* __restrict__ bias, int tid) {
    const int lane = tid & 31, wrp = tid >> 5;
    const int mw = wrp >> 1, nw = wrp & 1;
    const int gid4 = lane >> 2, tig = lane & 3;
    const int cw = mw * 16, pw = nw * 64;

    float acc[8][4];
#pragma unroll
    for (int nt = 0; nt < 8; nt++)
#pragma unroll
        for (int j = 0; j < 4; j++) acc[nt][j] = 0.0f;

#pragma unroll
    for (int kk = 0; kk < 4; kk++) {
        const int kpb = kk * 8;
        u32 ahi[4], alo[4];
        const int r0 = cw + gid4;
#pragma unroll
        for (int q = 0; q < 4; q++) {
            const int rr = r0 + (q & 1) * 8;
            const int kq = kpb + tig + (q >> 1) * 4;
            ahi[q] = wb[rr * WST + kq];
            alo[q] = wb[wplane + rr * WST + kq];
        }
        u32 bhi[8][2], blo[8][2];
#pragma unroll
        for (int nt = 0; nt < 8; nt++) {
            const int pp = pw + nt * 8 + gid4;
#pragma unroll
            for (int q = 0; q < 2; q++) {
                const int kr = kpb + tig + q * 4;
                bhi[nt][q] = actin[kr * AST + pp];
                blo[nt][q] = actin[ACT_PL + kr * AST + pp];
            }
        }
#pragma unroll
        for (int nt = 0; nt < 8; nt++) {
            mma16(acc[nt], ahi, bhi[nt]);
            mma16(acc[nt], ahi, blo[nt]);
            mma16(acc[nt], alo, bhi[nt]);
        }
    }
    char* outc = reinterpret_cast<char*>(actout);
#pragma unroll
    for (int hf = 0; hf < 2; hf++) {
        const int c = cw + gid4 + hf * 8;
        const float bias_c = __ldg(&bias[c]);
        const int half_off = (c & 1) * 2;
        const int kp_base = (c >> 1) * AST;
#pragma unroll
        for (int nt = 0; nt < 8; nt++)
#pragma unroll
            for (int jj = 0; jj < 2; jj++) {
                float val = fmaxf(fmaf(acc[nt][hf * 2 + jj], 0.015625f, bias_c), 0.0f);
                unsigned short hi, lo;
                split_limbs(val, hi, lo);
                const int pl = pw + nt * 8 + tig * 2 + jj;
                char* base = outc + (u32)((kp_base + pl) * 4 + half_off);
                *reinterpret_cast<unsigned short*>(base) = hi;
                *reinterpret_cast<unsigned short*>(base + ACT_PL * 4) = lo;
            }
    }
}

// L3: mainloop (MT=2) + fp32 stage write
__device__ __forceinline__ void layer_mma_stage(const u32* __restrict__ wb, int wplane,
                                                const u32* __restrict__ act,
                                                float* __restrict__ stage,
                                                const float* __restrict__ bias, int tid) {
    const int lane = tid & 31, wrp = tid >> 5;
    const int mw = wrp >> 1, nw = wrp & 1;
    const int gid4 = lane >> 2, tig = lane & 3;
    const int cw = mw * 32, pw = nw * 64;

    float acc[2][8][4];
#pragma unroll
    for (int mt = 0; mt < 2; mt++)
#pragma unroll
        for (int nt = 0; nt < 8; nt++)
#pragma unroll
            for (int j = 0; j < 4; j++) acc[mt][nt][j] = 0.0f;

#pragma unroll
    for (int kk = 0; kk < 4; kk++) {
        const int kpb = kk * 8;
        u32 ahi[2][4], alo[2][4];
#pragma unroll
        for (int mt = 0; mt < 2; mt++) {
            const int r0 = cw + mt * 16 + gid4;
#pragma unroll
            for (int q = 0; q < 4; q++) {
                const int rr = r0 + (q & 1) * 8;
                const int kq = kpb + tig + (q >> 1) * 4;
                ahi[mt][q] = wb[rr * WST + kq];
                alo[mt][q] = wb[wplane + rr * WST + kq];
            }
        }
        u32 bhi[8][2], blo[8][2];
#pragma unroll
        for (int nt = 0; nt < 8; nt++) {
            const int pp = pw + nt * 8 + gid4;
#pragma unroll
            for (int q = 0; q < 2; q++) {
                const int kr = kpb + tig + q * 4;
                bhi[nt][q] = act[kr * AST + pp];
                blo[nt][q] = act[ACT_PL + kr * AST + pp];
            }
        }
#pragma unroll
        for (int mt = 0; mt < 2; mt++)
#pragma unroll
            for (int nt = 0; nt < 8; nt++) {
                mma16(acc[mt][nt], ahi[mt], bhi[nt]);
                mma16(acc[mt][nt], ahi[mt], blo[nt]);
                mma16(acc[mt][nt], alo[mt], bhi[nt]);
            }
    }
#pragma unroll
    for (int mt = 0; mt < 2; mt++)
#pragma unroll
        for (int hf = 0; hf < 2; hf++) {
            const int c = cw + mt * 16 + gid4 + hf * 8;
            const float bias_c = __ldg(&bias[c]);
#pragma unroll
            for (int nt = 0; nt < 8; nt++)
#pragma unroll
                for (int jj = 0; jj < 2; jj++) {
                    float val = fmaxf(fmaf(acc[mt][nt][hf * 2 + jj], 0.015625f, bias_c), 0.0f);
                    stage[c * 130 + pw + nt * 8 + tig * 2 + jj] = val;
                }
        }
}

__global__ __launch_bounds__(256, 1)
void kA(const float* __restrict__ points,
        const float* __restrict__ wl0, const float* __restrict__ bl0,
        const float* __restrict__ bl1, const float* __restrict__ bl2,
        const float* __restrict__ bl3) {
    extern __shared__ u32 smu[];
    u32* wbufA = smu + OFF_WBA;
    u32* wbufB = smu + OFF_WBB;
    u32* wbufC = smu + OFF_WBC;
    u32* actA  = smu + OFF_ACTA;
    u32* actB  = smu + OFF_ACTB;
    float* stage = reinterpret_cast<float*>(smu + OFF_STAGE);
    float* w0buf = reinterpret_cast<float*>(smu + OFF_W0);
    const u32 sbase = smem_u32(smu);
    const int tid = threadIdx.x;

    // all weights loaded once, one group; overlaps tile-0 L0
    cpw(sbase + OFF_WBA * 4, g_w1hi, g_w1lo, 64, tid);
    cpw(sbase + OFF_WBB * 4, g_w2hi, g_w2lo, 64, tid);
    cpw(sbase + OFF_WBC * 4, g_w3hi, g_w3lo, 128, tid);
    CP_COMMIT();

    for (int i = tid; i < 448; i += 256) w0buf[i] = wl0[i];
    for (int i = tid; i < 64; i += 256) w0buf[448 + i] = bl0[i];
    __syncthreads();

#pragma unroll 1
    for (int t = 0; t < 2; t++) {
        const int T = blockIdx.x * 2 + t;
        const int b = T >> 7;
        const int pbase = (T & 127) * 128;

        // L0: 7 -> 64 scalar, direct limb act tile
        {
            const int pt = tid & 127, seg = tid >> 7;
            const float* ptp = points + (size_t)b * INC * NPTS + pbase + pt;
            float x[INC];
#pragma unroll
            for (int c = 0; c < INC; c++) x[c] = ptp[(size_t)c * NPTS];
            if (seg == 0) {
                int g = 0; float bv = x[3];
                if (x[4] > bv) { bv = x[4]; g = 1; }
                if (x[5] > bv) { bv = x[5]; g = 2; }
                if (x[6] > bv) { bv = x[6]; g = 3; }
                g_gid[b * NPTS + pbase + pt] = (unsigned char)g;
            }
#pragma unroll 4
            for (int kp = seg * 16; kp < seg * 16 + 16; kp++) {
                const int c = 2 * kp;
                const float* w0 = w0buf + c * 7;
                const float* w1 = w0 + 7;
                float s0 = w0buf[448 + c], s1 = w0buf[448 + c + 1];
#pragma unroll
                for (int k = 0; k < INC; k++) { s0 = fmaf(w0[k], x[k], s0); s1 = fmaf(w1[k], x[k], s1); }
                u32 hi, lo;
                split_pair(fmaxf(s0, 0.0f), fmaxf(s1, 0.0f), hi, lo);
                actA[kp * AST + pt] = hi;
                actA[ACT_PL + kp * AST + pt] = lo;
            }
        }
        if (t == 0) CP_WAIT0();
        __syncthreads();                    // actA visible (+ weights on t=0)

        layer_mma_act(wbufA, 64 * WST, actA, actB, bl1, tid);   // L1 -> actB
        __syncthreads();
        layer_mma_act(wbufB, 64 * WST, actB, actA, bl2, tid);   // L2 -> actA
        __syncthreads();
        layer_mma_stage(wbufC, 128 * WST, actA, stage, bl3, tid); // L3 -> stage
        __syncthreads();
        {
            const int pt = tid & 127, seg = tid >> 7;
#pragma unroll 4
            for (int kp = seg * 32; kp < seg * 32 + 32; kp++) {
                u32 hi, lo;
                split_pair(stage[(2 * kp) * 130 + pt], stage[(2 * kp + 1) * 130 + pt], hi, lo);
                g_hhi[((size_t)b * 64 + kp) * NPTS + pbase + pt] = hi;
                g_hlo[((size_t)b * 64 + kp) * NPTS + pbase + pt] = lo;
            }
        }
        __syncthreads();                    // stage + actA free for next tile
    }
}

// ================= kernel B: R13/R15 proven — DO NOT MODIFY =================
#define WS2 68
#define HS2 136
#define KB_W_U (2 * 128 * WS2)
#define KB_H_U (2 * 64 * HS2)
#define KB_SMEM_BYTES ((KB_W_U + 2 * KB_H_U) * 4)

__global__ __launch_bounds__(256, 1)
void kB(const float* __restrict__ bl4) {
    extern __shared__ float smf[];
    u32* swp = reinterpret_cast<u32*>(smf);
    u32* hbuf0 = swp + KB_W_U;
    u32* hbuf1 = hbuf0 + KB_H_U;
    __shared__ unsigned char gid_s[128];

    const int tid = threadIdx.x;
    const int bid = blockIdx.x;
    const int b  = bid >> 6;
    const int pg = (bid >> 3) & 7;
    const int cc = bid & 7;
    const int c0 = cc * 128;

#pragma unroll
    for (int j = 0; j < 8; j++) {
        int idx = j * 256 + tid;
        int r = idx >> 4, q = (idx & 15) * 4;
        uint4 vh = *reinterpret_cast<const uint4*>(g_wphi + (size_t)(c0 + r) * 64 + q);
        uint4 vl = *reinterpret_cast<const uint4*>(g_wplo + (size_t)(c0 + r) * 64 + q);
        *reinterpret_cast<uint4*>(&swp[r * WS2 + q]) = vh;
        *reinterpret_cast<uint4*>(&swp[128 * WS2 + r * WS2 + q]) = vl;
    }

    const u32 hadd[2] = { smem_u32(hbuf0), smem_u32(hbuf1) };
    {
        const int pbase = pg * 2048;
#pragma unroll
        for (int j = 0; j < 16; j++) {
            int idx = j * 256 + tid;
            int row = idx >> 5, q = (idx & 31) * 4;
            const u32* src = (row < 64)
                ? g_hhi + ((size_t)b * 64 + row) * NPTS + pbase + q
                : g_hlo + ((size_t)b * 64 + (row - 64)) * NPTS + pbase + q;
            CP_ASYNC16(hadd[0] + (u32)(row * HS2 + q) * 4, src);
        }
        CP_COMMIT();
    }

    const int lane = tid & 31, wrp = tid >> 5;
    const int mw = wrp >> 1;
    const int nw = wrp & 1;
    const int gid4 = lane >> 2, tig = lane & 3;
    const int cw = mw * 32, pw = nw * 64;

    float biasr[2][2];
    u64 pk[2][2];
    float gm[2][2][4];
#pragma unroll
    for (int mt = 0; mt < 2; mt++)
#pragma unroll
        for (int hf = 0; hf < 2; hf++) {
            biasr[mt][hf] = __ldg(&bl4[c0 + cw + mt * 16 + gid4 + hf * 8]);
            pk[mt][hf] = 0ull;
#pragma unroll
            for (int g = 0; g < 4; g++) gm[mt][hf][g] = 0.0f;
        }

#pragma unroll 1
    for (int t = 0; t < 16; t++) {
        const int pbase = (pg * 16 + t) * 128;
        u32* shp = (t & 1) ? hbuf1 : hbuf0;
        if (t + 1 < 16) {
            const int pn = (pg * 16 + t + 1) * 128;
            const u32 dsta = hadd[(t + 1) & 1];
#pragma unroll
            for (int j = 0; j < 16; j++) {
                int idx = j * 256 + tid;
                int row = idx >> 5, q = (idx & 31) * 4;
                const u32* src = (row < 64)
                    ? g_hhi + ((size_t)b * 64 + row) * NPTS + pn + q
                    : g_hlo + ((size_t)b * 64 + (row - 64)) * NPTS + pn + q;
                CP_ASYNC16(dsta + (u32)(row * HS2 + q) * 4, src);
            }
            CP_COMMIT();
            CP_WAIT1();
        } else {
            CP_WAIT0();
        }
        if (tid < 128) gid_s[tid] = g_gid[b * NPTS + pbase + tid];
        __syncthreads();

        float acc[2][8][4];
#pragma unroll
        for (int mt = 0; mt < 2; mt++)
#pragma unroll
            for (int nt = 0; nt < 8; nt++)
#pragma unroll
                for (int j = 0; j < 4; j++) acc[mt][nt][j] = 0.0f;

        const u32* swhi = swp;
        const u32* swlo = swp + 128 * WS2;
        const u32* shhi = shp;
        const u32* shlo = shp + 64 * HS2;

#pragma unroll 1
        for (int kk = 0; kk < 8; kk++) {
            const int kpb = kk * 8;
            u32 ahi[2][4], alo[2][4];
#pragma unroll
            for (int mt = 0; mt < 2; mt++) {
                const int r0 = cw + mt * 16 + gid4;
#pragma unroll
                for (int q = 0; q < 4; q++) {
                    const int rr = r0 + (q & 1) * 8;
                    const int kq = kpb + tig + (q >> 1) * 4;
                    ahi[mt][q] = swhi[rr * WS2 + kq];
                    alo[mt][q] = swlo[rr * WS2 + kq];
                }
            }
            u32 bhi[8][2], blo[8][2];
#pragma unroll
            for (int nt = 0; nt < 8; nt++) {
                const int pp = pw + nt * 8 + gid4;
#pragma unroll
                for (int q = 0; q < 2; q++) {
                    const int kr = kpb + tig + q * 4;
                    bhi[nt][q] = shhi[kr * HS2 + pp];
                    blo[nt][q] = shlo[kr * HS2 + pp];
                }
            }
#pragma unroll
            for (int mt = 0; mt < 2; mt++)
#pragma unroll
                for (int nt = 0; nt < 8; nt++) {
                    mma16(acc[mt][nt], ahi[mt], bhi[nt]);
                    mma16(acc[mt][nt], ahi[mt], blo[nt]);
                    mma16(acc[mt][nt], alo[mt], bhi[nt]);
                }
        }

#pragma unroll
        for (int mt = 0; mt < 2; mt++)
#pragma unroll
            for (int hf = 0; hf < 2; hf++) {
                const float bias_c = biasr[mt][hf];
                u64 key = pk[mt][hf];
                float g0 = gm[mt][hf][0], g1 = gm[mt][hf][1];
                float g2 = gm[mt][hf][2], g3 = gm[mt][hf][3];
#pragma unroll
                for (int nt = 0; nt < 8; nt++)
#pragma unroll
                    for (int jj = 0; jj < 2; jj++) {
                        float val = fmaxf(fmaf(acc[mt][nt][hf * 2 + jj], 0.015625f, bias_c), 0.0f);
                        const int pl = pw + nt * 8 + tig * 2 + jj;
                        u64 k = ((u64)__float_as_uint(val) << 32) |
                                (u64)(0xFFFFFFFFu - (u32)(pbase + pl));
                        if (k > key) key = k;
                        const int gi = gid_s[pl];
                        g0 = fmaxf(g0, gi == 0 ? val : 0.f);
                        g1 = fmaxf(g1, gi == 1 ? val : 0.f);
                        g2 = fmaxf(g2, gi == 2 ? val : 0.f);
                        g3 = fmaxf(g3, gi == 3 ? val : 0.f);
                    }
                pk[mt][hf] = key;
                gm[mt][hf][0] = g0; gm[mt][hf][1] = g1;
                gm[mt][hf][2] = g2; gm[mt][hf][3] = g3;
            }
        __syncthreads();
    }

    u64* skey = reinterpret_cast<u64*>(hbuf0);
    float* sg = reinterpret_cast<float*>(skey + 1024);
    const int slot = nw * 4 + tig;
#pragma unroll
    for (int mt = 0; mt < 2; mt++)
#pragma unroll
        for (int hf = 0; hf < 2; hf++) {
            const int c = cw + mt * 16 + gid4 + hf * 8;
            skey[c * 8 + slot] = pk[mt][hf];
#pragma unroll
            for (int g = 0; g < 4; g++) sg[(c * 8 + slot) * 4 + g] = gm[mt][hf][g];
        }
    __syncthreads();

    if (tid < 128) {
        const int c = tid;
        u64 m = skey[c * 8];
        float mg[4] = { sg[c * 32 + 0], sg[c * 32 + 1], sg[c * 32 + 2], sg[c * 32 + 3] };
#pragma unroll
        for (int q = 1; q < 8; q++) {
            u64 e = skey[c * 8 + q];
            if (e > m) m = e;
#pragma unroll
            for (int g = 0; g < 4; g++) mg[g] = fmaxf(mg[g], sg[(c * 8 + q) * 4 + g]);
        }
        atomicMax(&g_pmax[b * 1024 + c0 + c], m);
#pragma unroll
        for (int g = 0; g < 4; g++)
            atomicMax(&g_gmax[g * 1024 + c0 + c], __float_as_uint(mg[g]));
    }
}

// ---------------- tail MLPs (R15 proven scalar) ----------------
__global__ void kC1(const float* __restrict__ wg0, const float* __restrict__ bg0,
                    const float* __restrict__ wgr0, const float* __restrict__ bgr0,
                    float* __restrict__ out) {
    const int gtid = blockIdx.x * blockDim.x + threadIdx.x;
    if (gtid < BATCH * 1024) {
        unsigned long long pv = g_pmax[gtid];
        out[4096 + gtid] = (float)(0xFFFFFFFFu - (unsigned int)(pv & 0xFFFFFFFFull));
    }
    const int wid = gtid >> 5;
    const int lane = gtid & 31;
    const int row = wid >> 9;
    const int j = wid & 511;
    if (row > 16) return;
    float s = 0.0f;
    if (row < 16) {
        const float* wr = wg0 + (size_t)j * 1024;
        const unsigned long long* pbuf = g_pmax + row * 1024;
        for (int k = lane; k < 1024; k += 32)
            s = fmaf(wr[k], __uint_as_float((unsigned int)(pbuf[k] >> 32)), s);
    } else {
        const float* wr = wgr0 + (size_t)j * 4096;
        for (int k = lane; k < 4096; k += 32)
            s = fmaf(wr[k], __uint_as_float(g_gmax[k]), s);
    }
#pragma unroll
    for (int o = 16; o; o >>= 1) s += __shfl_xor_sync(0xFFFFFFFFu, s, o);
    if (lane == 0) {
        float bb = (row < 16) ? bg0[j] : bgr0[j];
        g_u1[row * 512 + j] = fmaxf(s + bb, 0.0f);
    }
}

__global__ void kC2(const float* __restrict__ wg1, const float* __restrict__ bg1,
                    const float* __restrict__ wgr1, const float* __restrict__ bgr1,
                    float* __restrict__ out) {
    const int gtid = blockIdx.x * blockDim.x + threadIdx.x;
    const int wid = gtid >> 5;
    const int lane = gtid & 31;
    const int row = wid >> 7;
    const int j = wid & 127;
    if (row > 16) return;
    const float* wr = ((row < 16) ? wg1 : wgr1) + (size_t)j * 512;
    const float* in = g_u1 + row * 512;
    float s = 0.0f;
    for (int k = lane; k < 512; k += 32) s = fmaf(wr[k], in[k], s);
#pragma unroll
    for (int o = 16; o; o >>= 1) s += __shfl_xor_sync(0xFFFFFFFFu, s, o);
    s = __shfl_sync(0xFFFFFFFFu, s, 0);
    float bb = (row < 16) ? bg1[j] : bgr1[j];
    float val = fmaxf(s + bb, 0.0f);
    if (row < 16) {
        if (lane == 0) out[row * 256 + 128 + j] = val;
    } else {
        if (lane < 16) out[lane * 256 + j] = val;
    }
}

// ---------------- launch ----------------
extern "C" void kernel_launch(void* const* d_in, const int* in_sizes, int n_in,
                              void* d_out, int out_size) {
    const float* points = (const float*)d_in[0];
    const float* wl0 = (const float*)d_in[1];  const float* bl0 = (const float*)d_in[2];
    const float* wl1 = (const float*)d_in[3];  const float* bl1 = (const float*)d_in[4];
    const float* wl2 = (const float*)d_in[5];  const float* bl2 = (const float*)d_in[6];
    const float* wl3 = (const float*)d_in[7];  const float* bl3 = (const float*)d_in[8];
    const float* wl4 = (const float*)d_in[9];  const float* bl4 = (const float*)d_in[10];
    const float* wg0 = (const float*)d_in[11]; const float* bg0 = (const float*)d_in[12];
    const float* wg1 = (const float*)d_in[13]; const float* bg1 = (const float*)d_in[14];
    const float* wgr0 = (const float*)d_in[15]; const float* bgr0 = (const float*)d_in[16];
    const float* wgr1 = (const float*)d_in[17]; const float* bgr1 = (const float*)d_in[18];
    float* out = (float*)d_out;

    cudaFuncSetAttribute(kA, cudaFuncAttributeMaxDynamicSharedMemorySize,
                         KA_SMEM_U32 * (int)sizeof(u32));
    cudaFuncSetAttribute(kB, cudaFuncAttributeMaxDynamicSharedMemorySize, KB_SMEM_BYTES);

    kWall<<<288, 256>>>(wl1, wl2, wl3, wl4);
    kA<<<BATCH * NPTS / 256, 256, KA_SMEM_U32 * sizeof(u32)>>>(
        points, wl0, bl0, bl1, bl2, bl3);
    kB<<<1024, 256, KB_SMEM_BYTES>>>(bl4);
    kC1<<<1088, 256>>>(wg0, bg0, wgr0, bgr0, out);
    kC2<<<272, 256>>>(wg1, bg1, wgr1, bgr1, out);
}